// round 2
// baseline (speedup 1.0000x reference)
#include <cuda_runtime.h>
#include <math.h>

// ---------------------------------------------------------------------------
// Scratch (allocation-free rule: device globals)
// ---------------------------------------------------------------------------
__device__ float g_qkv[4096 * 3072];   // [B*S, 3D]  Q|K|V column blocks
__device__ float g_attn[4096 * 1024];  // [B*S, D]   attention output (b,s,(h d))

// ---------------------------------------------------------------------------
// SGEMM  C[M,N] = A[M,K] @ B[N,K]^T   (all row-major, fp32)
// 128x128 block, BK=16, 256 threads, 8x8 per-thread microtile.
// Assumes M%128==0, N%128==0, K%16==0 (true for all our shapes).
// ---------------------------------------------------------------------------
#define GBM 128
#define GBN 128
#define GBK 16

__global__ __launch_bounds__(256) void sgemm_nt(const float* __restrict__ A,
                                                const float* __restrict__ B,
                                                float* __restrict__ C,
                                                int M, int N, int K) {
    __shared__ float As[GBK][GBM];
    __shared__ float Bs[GBK][GBN];
    const int tid = threadIdx.x;
    const int tx = tid & 15, ty = tid >> 4;
    const int row0 = blockIdx.y * GBM;
    const int col0 = blockIdx.x * GBN;

    float acc[8][8] = {};

    const int lr  = tid >> 2;         // 0..63
    const int lc4 = (tid & 3) << 2;   // 0,4,8,12

    for (int k0 = 0; k0 < K; k0 += GBK) {
#pragma unroll
        for (int i = 0; i < 2; i++) {
            int r = lr + i * 64;
            float4 a = *(const float4*)&A[(size_t)(row0 + r) * K + k0 + lc4];
            As[lc4 + 0][r] = a.x; As[lc4 + 1][r] = a.y;
            As[lc4 + 2][r] = a.z; As[lc4 + 3][r] = a.w;
            float4 b = *(const float4*)&B[(size_t)(col0 + r) * K + k0 + lc4];
            Bs[lc4 + 0][r] = b.x; Bs[lc4 + 1][r] = b.y;
            Bs[lc4 + 2][r] = b.z; Bs[lc4 + 3][r] = b.w;
        }
        __syncthreads();
#pragma unroll
        for (int k = 0; k < GBK; k++) {
            float4 a0 = *(const float4*)&As[k][ty * 8];
            float4 a1 = *(const float4*)&As[k][ty * 8 + 4];
            float4 b0 = *(const float4*)&Bs[k][tx * 8];
            float4 b1 = *(const float4*)&Bs[k][tx * 8 + 4];
            float ra[8] = {a0.x, a0.y, a0.z, a0.w, a1.x, a1.y, a1.z, a1.w};
            float rb[8] = {b0.x, b0.y, b0.z, b0.w, b1.x, b1.y, b1.z, b1.w};
#pragma unroll
            for (int i = 0; i < 8; i++)
#pragma unroll
                for (int j = 0; j < 8; j++)
                    acc[i][j] += ra[i] * rb[j];
        }
        __syncthreads();
    }

#pragma unroll
    for (int i = 0; i < 8; i++) {
        int r = row0 + ty * 8 + i;
#pragma unroll
        for (int j = 0; j < 8; j += 4) {
            float4 v = make_float4(acc[i][j], acc[i][j + 1], acc[i][j + 2], acc[i][j + 3]);
            *(float4*)&C[(size_t)r * N + col0 + tx * 8 + j] = v;
        }
    }
}

// ---------------------------------------------------------------------------
// Flash attention (fp32, non-causal).
//   qkv: [B*S, 3072] with Q at cols [0,1024), K [1024,2048), V [2048,3072)
//   out: [B*S, 1024]  laid out (b, s, h*64+d)  -> directly feeds out-proj GEMM
// Block: 64 query rows x full key loop (32 tiles of 64). 256 threads.
// S tile aliases the K tile -> 3*16KB + reductions ~= 50KB dynamic smem.
// ---------------------------------------------------------------------------
__global__ __launch_bounds__(256) void flash_attn(const float* __restrict__ qkv,
                                                  float* __restrict__ attn_out) {
    extern __shared__ float sm[];
    float* Qs   = sm;            // [64][64]  Qs[d][r]   (transposed, pre-scaled)
    float* Ks   = Qs + 4096;     // [64][64]  Ks[d][c]   (transposed) -- aliased as Ss
    float* Vs   = Ks + 4096;     // [64][64]  Vs[k][d]   (natural)
    float* red  = Vs + 4096;     // [64*4] partial reductions
    float* mrow = red + 256;     // [64] running max
    float* lrow = mrow + 64;     // [64] running sum
    float* arow = lrow + 64;     // [64] rescale alpha
    float* Ss   = Ks;            // alias: scores/probs [r][c]

    const int tid = threadIdx.x;
    const int tx = tid & 15, ty = tid >> 4;
    const int r0 = ty * 4, c0 = tx * 4;
    const int qt = blockIdx.x;            // query tile 0..31
    const int b  = blockIdx.y >> 4;
    const int h  = blockIdx.y & 15;

    const float* base = qkv + (size_t)b * 2048 * 3072;
    const int qoff = h * 64;
    const int koff = 1024 + h * 64;
    const int voff = 2048 + h * 64;

    // Load Q tile (transposed + scaled by 1/sqrt(64))
#pragma unroll
    for (int i = 0; i < 4; i++) {
        int idx = tid + i * 256;          // 0..1023
        int r = idx >> 4;
        int c4 = (idx & 15) << 2;
        float4 v = *(const float4*)&base[(size_t)(qt * 64 + r) * 3072 + qoff + c4];
        Qs[(c4 + 0) * 64 + r] = v.x * 0.125f;
        Qs[(c4 + 1) * 64 + r] = v.y * 0.125f;
        Qs[(c4 + 2) * 64 + r] = v.z * 0.125f;
        Qs[(c4 + 3) * 64 + r] = v.w * 0.125f;
    }
    if (tid < 64) { mrow[tid] = -1e30f; lrow[tid] = 0.0f; }

    float o[4][4] = {};

    for (int kt = 0; kt < 32; kt++) {
        __syncthreads();  // prev-iter Ss/Vs consumers done; Q/m/l init visible (kt=0)

        // Load K (transposed) and V (natural) tiles
#pragma unroll
        for (int i = 0; i < 4; i++) {
            int idx = tid + i * 256;
            int r = idx >> 4;
            int c4 = (idx & 15) << 2;
            float4 kv = *(const float4*)&base[(size_t)(kt * 64 + r) * 3072 + koff + c4];
            Ks[(c4 + 0) * 64 + r] = kv.x;
            Ks[(c4 + 1) * 64 + r] = kv.y;
            Ks[(c4 + 2) * 64 + r] = kv.z;
            Ks[(c4 + 3) * 64 + r] = kv.w;
            float4 vv = *(const float4*)&base[(size_t)(kt * 64 + r) * 3072 + voff + c4];
            *(float4*)&Vs[r * 64 + c4] = vv;
        }
        __syncthreads();

        // S = Q @ K^T  (4x4 microtile per thread)
        float s[4][4] = {};
#pragma unroll
        for (int d = 0; d < 64; d++) {
            float4 qv = *(const float4*)&Qs[d * 64 + r0];
            float4 kv = *(const float4*)&Ks[d * 64 + c0];
            float ra[4] = {qv.x, qv.y, qv.z, qv.w};
            float rb[4] = {kv.x, kv.y, kv.z, kv.w};
#pragma unroll
            for (int i = 0; i < 4; i++)
#pragma unroll
                for (int j = 0; j < 4; j++)
                    s[i][j] += ra[i] * rb[j];
        }
        __syncthreads();  // everyone done reading Ks before it becomes Ss

#pragma unroll
        for (int i = 0; i < 4; i++)
            *(float4*)&Ss[(r0 + i) * 64 + c0] =
                make_float4(s[i][0], s[i][1], s[i][2], s[i][3]);
        __syncthreads();

        // Row max (partial: 4 threads per row x 16 cols)
        {
            int row = tid >> 2, q = tid & 3;
            const float* p = &Ss[row * 64 + q * 16];
            float m = p[0];
#pragma unroll
            for (int t = 1; t < 16; t++) m = fmaxf(m, p[t]);
            red[row * 4 + q] = m;
        }
        __syncthreads();
        if (tid < 64) {
            float m_new = fmaxf(fmaxf(red[tid * 4], red[tid * 4 + 1]),
                                fmaxf(red[tid * 4 + 2], red[tid * 4 + 3]));
            m_new = fmaxf(m_new, mrow[tid]);
            arow[tid] = __expf(mrow[tid] - m_new);
            mrow[tid] = m_new;
        }
        __syncthreads();

        // exp in place + partial row sums
        {
            int row = tid >> 2, q = tid & 3;
            float m = mrow[row];
            float* p = &Ss[row * 64 + q * 16];
            float sum = 0.0f;
#pragma unroll
            for (int t = 0; t < 16; t++) {
                float e = __expf(p[t] - m);
                p[t] = e;
                sum += e;
            }
            red[row * 4 + q] = sum;
        }
        __syncthreads();
        if (tid < 64)
            lrow[tid] = lrow[tid] * arow[tid] +
                        red[tid * 4] + red[tid * 4 + 1] + red[tid * 4 + 2] + red[tid * 4 + 3];

        // O = O*alpha + P @ V
#pragma unroll
        for (int i = 0; i < 4; i++) {
            float a = arow[r0 + i];
#pragma unroll
            for (int j = 0; j < 4; j++) o[i][j] *= a;
        }
#pragma unroll
        for (int kk = 0; kk < 64; kk++) {
            float4 vv = *(const float4*)&Vs[kk * 64 + c0];
            float rv[4] = {vv.x, vv.y, vv.z, vv.w};
#pragma unroll
            for (int i = 0; i < 4; i++) {
                float p = Ss[(r0 + i) * 64 + kk];
#pragma unroll
                for (int j = 0; j < 4; j++) o[i][j] += p * rv[j];
            }
        }
    }
    __syncthreads();

    // Normalize and store (b, s, h*64+d)
#pragma unroll
    for (int i = 0; i < 4; i++) {
        float inv = 1.0f / lrow[r0 + i];
        float4 v = make_float4(o[i][0] * inv, o[i][1] * inv, o[i][2] * inv, o[i][3] * inv);
        *(float4*)&attn_out[(size_t)(b * 2048 + qt * 64 + r0 + i) * 1024 + h * 64 + c0] = v;
    }
}

// ---------------------------------------------------------------------------
// Launch: QKV GEMM -> flash attention -> output GEMM
// ---------------------------------------------------------------------------
extern "C" void kernel_launch(void* const* d_in, const int* in_sizes, int n_in,
                              void* d_out, int out_size) {
    const float* x     = (const float*)d_in[0];  // [2,2048,1024]
    const float* w_qkv = (const float*)d_in[1];  // [3072,1024]
    const float* w_out = (const float*)d_in[2];  // [1024,1024]
    float* out = (float*)d_out;                  // [2,2048,1024]

    float* qkv  = nullptr;
    float* attn = nullptr;
    cudaGetSymbolAddress((void**)&qkv, g_qkv);
    cudaGetSymbolAddress((void**)&attn, g_attn);

    const size_t FLASH_SMEM = (3 * 4096 + 256 + 3 * 64) * sizeof(float);  // 50944 B
    cudaFuncSetAttribute(flash_attn, cudaFuncAttributeMaxDynamicSharedMemorySize,
                         (int)FLASH_SMEM);

    dim3 blk(256);
    // QKV: [4096,3072] = x[4096,1024] @ w_qkv[3072,1024]^T
    sgemm_nt<<<dim3(3072 / GBN, 4096 / GBM), blk>>>(x, w_qkv, qkv, 4096, 3072, 1024);
    // Attention: 32 q-tiles x (B*H = 32)
    flash_attn<<<dim3(32, 32), blk, FLASH_SMEM>>>(qkv, attn);
    // Out: [4096,1024] = attn[4096,1024] @ w_out[1024,1024]^T
    sgemm_nt<<<dim3(1024 / GBN, 4096 / GBM), blk>>>(attn, w_out, out, 4096, 1024, 1024);
}

// round 6
// speedup vs baseline: 1.2150x; 1.2150x over previous
#include <cuda_runtime.h>
#include <cuda_bf16.h>
#include <mma.h>
#include <math.h>
#include <stdint.h>

using namespace nvcuda;

// ---------------------------------------------------------------------------
// Scratch (allocation-free rule: device globals)
// ---------------------------------------------------------------------------
__device__ float g_qkv[4096 * 3072];   // [B*S, 3D]  Q|K|V column blocks
__device__ float g_attn[4096 * 1024];  // [B*S, D]   attention output (b,s,(h d))

// ---------------------------------------------------------------------------
// fp32 -> bf16 hi/lo split helpers
// ---------------------------------------------------------------------------
__device__ __forceinline__ uint32_t pack_bf16(float a, float b) {
    __nv_bfloat16 ha = __float2bfloat16_rn(a), hb = __float2bfloat16_rn(b);
    uint16_t ua = *(uint16_t*)&ha, ub = *(uint16_t*)&hb;
    return (uint32_t)ua | ((uint32_t)ub << 16);
}
__device__ __forceinline__ void split4(float4 v, uint2& hi, uint2& lo) {
    __nv_bfloat16 h0 = __float2bfloat16_rn(v.x), h1 = __float2bfloat16_rn(v.y);
    __nv_bfloat16 h2 = __float2bfloat16_rn(v.z), h3 = __float2bfloat16_rn(v.w);
    float l0 = v.x - __bfloat162float(h0), l1 = v.y - __bfloat162float(h1);
    float l2 = v.z - __bfloat162float(h2), l3 = v.w - __bfloat162float(h3);
    uint16_t u0 = *(uint16_t*)&h0, u1 = *(uint16_t*)&h1;
    uint16_t u2 = *(uint16_t*)&h2, u3 = *(uint16_t*)&h3;
    hi.x = (uint32_t)u0 | ((uint32_t)u1 << 16);
    hi.y = (uint32_t)u2 | ((uint32_t)u3 << 16);
    lo.x = pack_bf16(l0, l1);
    lo.y = pack_bf16(l2, l3);
}

// ---------------------------------------------------------------------------
// bf16x3 split GEMM via wmma (HMMA, base sm_103 ISA — tcgen05 is rejected by
// this harness's compute_103 PTX target).
//   C[M,N] = A[M,K] @ B[N,K]^T   fp32 in/out, fp32 accumulate on tensor pipe.
// 128x128 CTA tile, BK=16, 8 warps, warp tile 64x32.
// Per K-step: acc += Ah*Bh + Ah*Bl + Al*Bh  (error ~2^-16 relative)
// ---------------------------------------------------------------------------
#define LDA 24   // 16 data + 8 pad bf16 elems: 48B rows -> conflict-free ldmatrix

__global__ __launch_bounds__(256) void gemm_wmma(const float* __restrict__ A,
                                                 const float* __restrict__ B,
                                                 float* __restrict__ C,
                                                 int K, int N) {
    __shared__ alignas(128) __nv_bfloat16 Ah[128 * LDA];
    __shared__ alignas(128) __nv_bfloat16 Al[128 * LDA];
    __shared__ alignas(128) __nv_bfloat16 Bh[128 * LDA];
    __shared__ alignas(128) __nv_bfloat16 Bl[128 * LDA];

    const int tid = threadIdx.x;
    const int wid = tid >> 5;
    const int warp_row = wid >> 2;   // 0..1 -> 64 rows
    const int warp_col = wid & 3;    // 0..3 -> 32 cols
    const int row0 = blockIdx.y * 128;
    const int col0 = blockIdx.x * 128;

    wmma::fragment<wmma::accumulator, 16, 16, 16, float> acc[4][2];
#pragma unroll
    for (int i = 0; i < 4; i++)
#pragma unroll
        for (int j = 0; j < 2; j++) wmma::fill_fragment(acc[i][j], 0.0f);

    // per-chunk staging: 128 rows x 16 cols fp32 for A and B = 2 float4/thread each
    float4 pa[2], pb[2];
    const int NCH = K >> 4;

    auto gload = [&](int kc) {
#pragma unroll
        for (int i = 0; i < 2; i++) {
            int idx = tid + i * 256;        // 0..511 float4s
            int r = idx >> 2;               // 0..127
            int c4 = (idx & 3) << 2;        // 0,4,8,12
            pa[i] = *(const float4*)&A[(size_t)(row0 + r) * K + kc * 16 + c4];
            pb[i] = *(const float4*)&B[(size_t)(col0 + r) * K + kc * 16 + c4];
        }
    };
    auto sstore = [&]() {
#pragma unroll
        for (int i = 0; i < 2; i++) {
            int idx = tid + i * 256;
            int r = idx >> 2;
            int c4 = (idx & 3) << 2;
            uint2 hi, lo;
            split4(pa[i], hi, lo);
            *(uint2*)&Ah[r * LDA + c4] = hi;   // offset multiple of 4 elems -> 8B aligned
            *(uint2*)&Al[r * LDA + c4] = lo;
            split4(pb[i], hi, lo);
            *(uint2*)&Bh[r * LDA + c4] = hi;
            *(uint2*)&Bl[r * LDA + c4] = lo;
        }
    };

    gload(0);
    for (int c = 0; c < NCH; c++) {
        __syncthreads();   // previous chunk's fragment loads done
        sstore();
        __syncthreads();
        if (c + 1 < NCH) gload(c + 1);   // overlap next loads with HMMAs

        wmma::fragment<wmma::matrix_a, 16, 16, 16, __nv_bfloat16, wmma::row_major> ah[4], al[4];
        wmma::fragment<wmma::matrix_b, 16, 16, 16, __nv_bfloat16, wmma::col_major> bh[2], bl[2];
#pragma unroll
        for (int i = 0; i < 4; i++) {
            int r = warp_row * 64 + i * 16;
            wmma::load_matrix_sync(ah[i], &Ah[r * LDA], LDA);
            wmma::load_matrix_sync(al[i], &Al[r * LDA], LDA);
        }
#pragma unroll
        for (int j = 0; j < 2; j++) {
            int cc = warp_col * 32 + j * 16;
            wmma::load_matrix_sync(bh[j], &Bh[cc * LDA], LDA);
            wmma::load_matrix_sync(bl[j], &Bl[cc * LDA], LDA);
        }
#pragma unroll
        for (int i = 0; i < 4; i++)
#pragma unroll
            for (int j = 0; j < 2; j++) {
                wmma::mma_sync(acc[i][j], ah[i], bh[j], acc[i][j]);
                wmma::mma_sync(acc[i][j], ah[i], bl[j], acc[i][j]);
                wmma::mma_sync(acc[i][j], al[i], bh[j], acc[i][j]);
            }
    }

#pragma unroll
    for (int i = 0; i < 4; i++)
#pragma unroll
        for (int j = 0; j < 2; j++) {
            int r = row0 + warp_row * 64 + i * 16;
            int cc = col0 + warp_col * 32 + j * 16;
            wmma::store_matrix_sync(&C[(size_t)r * N + cc], acc[i][j], N, wmma::mem_row_major);
        }
}

// ---------------------------------------------------------------------------
// Flash attention (fp32, non-causal) — unchanged (known-good)
// ---------------------------------------------------------------------------
__global__ __launch_bounds__(256) void flash_attn(const float* __restrict__ qkv,
                                                  float* __restrict__ attn_out) {
    extern __shared__ float sm[];
    float* Qs   = sm;
    float* Ks   = Qs + 4096;
    float* Vs   = Ks + 4096;
    float* red  = Vs + 4096;
    float* mrow = red + 256;
    float* lrow = mrow + 64;
    float* arow = lrow + 64;
    float* Ss   = Ks;

    const int tid = threadIdx.x;
    const int tx = tid & 15, ty = tid >> 4;
    const int r0 = ty * 4, c0 = tx * 4;
    const int qt = blockIdx.x;
    const int b  = blockIdx.y >> 4;
    const int h  = blockIdx.y & 15;

    const float* base = qkv + (size_t)b * 2048 * 3072;
    const int qoff = h * 64;
    const int koff = 1024 + h * 64;
    const int voff = 2048 + h * 64;

#pragma unroll
    for (int i = 0; i < 4; i++) {
        int idx = tid + i * 256;
        int r = idx >> 4;
        int c4 = (idx & 15) << 2;
        float4 v = *(const float4*)&base[(size_t)(qt * 64 + r) * 3072 + qoff + c4];
        Qs[(c4 + 0) * 64 + r] = v.x * 0.125f;
        Qs[(c4 + 1) * 64 + r] = v.y * 0.125f;
        Qs[(c4 + 2) * 64 + r] = v.z * 0.125f;
        Qs[(c4 + 3) * 64 + r] = v.w * 0.125f;
    }
    if (tid < 64) { mrow[tid] = -1e30f; lrow[tid] = 0.0f; }

    float o[4][4] = {};

    for (int kt = 0; kt < 32; kt++) {
        __syncthreads();
#pragma unroll
        for (int i = 0; i < 4; i++) {
            int idx = tid + i * 256;
            int r = idx >> 4;
            int c4 = (idx & 15) << 2;
            float4 kv = *(const float4*)&base[(size_t)(kt * 64 + r) * 3072 + koff + c4];
            Ks[(c4 + 0) * 64 + r] = kv.x;
            Ks[(c4 + 1) * 64 + r] = kv.y;
            Ks[(c4 + 2) * 64 + r] = kv.z;
            Ks[(c4 + 3) * 64 + r] = kv.w;
            float4 vv = *(const float4*)&base[(size_t)(kt * 64 + r) * 3072 + voff + c4];
            *(float4*)&Vs[r * 64 + c4] = vv;
        }
        __syncthreads();

        float s[4][4] = {};
#pragma unroll
        for (int d = 0; d < 64; d++) {
            float4 qv = *(const float4*)&Qs[d * 64 + r0];
            float4 kv = *(const float4*)&Ks[d * 64 + c0];
            float ra[4] = {qv.x, qv.y, qv.z, qv.w};
            float rb[4] = {kv.x, kv.y, kv.z, kv.w};
#pragma unroll
            for (int i = 0; i < 4; i++)
#pragma unroll
                for (int j = 0; j < 4; j++)
                    s[i][j] += ra[i] * rb[j];
        }
        __syncthreads();

#pragma unroll
        for (int i = 0; i < 4; i++)
            *(float4*)&Ss[(r0 + i) * 64 + c0] =
                make_float4(s[i][0], s[i][1], s[i][2], s[i][3]);
        __syncthreads();

        {
            int row = tid >> 2, q = tid & 3;
            const float* p = &Ss[row * 64 + q * 16];
            float m = p[0];
#pragma unroll
            for (int t = 1; t < 16; t++) m = fmaxf(m, p[t]);
            red[row * 4 + q] = m;
        }
        __syncthreads();
        if (tid < 64) {
            float m_new = fmaxf(fmaxf(red[tid * 4], red[tid * 4 + 1]),
                                fmaxf(red[tid * 4 + 2], red[tid * 4 + 3]));
            m_new = fmaxf(m_new, mrow[tid]);
            arow[tid] = __expf(mrow[tid] - m_new);
            mrow[tid] = m_new;
        }
        __syncthreads();

        {
            int row = tid >> 2, q = tid & 3;
            float m = mrow[row];
            float* p = &Ss[row * 64 + q * 16];
            float sum = 0.0f;
#pragma unroll
            for (int t = 0; t < 16; t++) {
                float e = __expf(p[t] - m);
                p[t] = e;
                sum += e;
            }
            red[row * 4 + q] = sum;
        }
        __syncthreads();
        if (tid < 64)
            lrow[tid] = lrow[tid] * arow[tid] +
                        red[tid * 4] + red[tid * 4 + 1] + red[tid * 4 + 2] + red[tid * 4 + 3];

#pragma unroll
        for (int i = 0; i < 4; i++) {
            float a = arow[r0 + i];
#pragma unroll
            for (int j = 0; j < 4; j++) o[i][j] *= a;
        }
#pragma unroll
        for (int kk = 0; kk < 64; kk++) {
            float4 vv = *(const float4*)&Vs[kk * 64 + c0];
            float rv[4] = {vv.x, vv.y, vv.z, vv.w};
#pragma unroll
            for (int i = 0; i < 4; i++) {
                float p = Ss[(r0 + i) * 64 + kk];
#pragma unroll
                for (int j = 0; j < 4; j++) o[i][j] += p * rv[j];
            }
        }
    }
    __syncthreads();

#pragma unroll
    for (int i = 0; i < 4; i++) {
        float inv = 1.0f / lrow[r0 + i];
        float4 v = make_float4(o[i][0] * inv, o[i][1] * inv, o[i][2] * inv, o[i][3] * inv);
        *(float4*)&attn_out[(size_t)(b * 2048 + qt * 64 + r0 + i) * 1024 + h * 64 + c0] = v;
    }
}

// ---------------------------------------------------------------------------
// Launch: QKV GEMM (wmma bf16x3) -> flash attention -> output GEMM (wmma)
// ---------------------------------------------------------------------------
extern "C" void kernel_launch(void* const* d_in, const int* in_sizes, int n_in,
                              void* d_out, int out_size) {
    const float* x     = (const float*)d_in[0];  // [2,2048,1024]
    const float* w_qkv = (const float*)d_in[1];  // [3072,1024]
    const float* w_out = (const float*)d_in[2];  // [1024,1024]
    float* out = (float*)d_out;                  // [2,2048,1024]

    float* qkv  = nullptr;
    float* attn = nullptr;
    cudaGetSymbolAddress((void**)&qkv, g_qkv);
    cudaGetSymbolAddress((void**)&attn, g_attn);

    const size_t FLASH_SMEM = (3 * 4096 + 256 + 3 * 64) * sizeof(float);  // 50944 B
    cudaFuncSetAttribute(flash_attn, cudaFuncAttributeMaxDynamicSharedMemorySize,
                         (int)FLASH_SMEM);

    dim3 blk(256);
    // QKV: [4096,3072] = x[4096,1024] @ w_qkv[3072,1024]^T
    gemm_wmma<<<dim3(3072 / 128, 4096 / 128), blk>>>(x, w_qkv, qkv, 1024, 3072);
    // Attention: 32 q-tiles x (B*H = 32)
    flash_attn<<<dim3(32, 32), blk, FLASH_SMEM>>>(qkv, attn);
    // Out: [4096,1024] = attn[4096,1024] @ w_out[1024,1024]^T
    gemm_wmma<<<dim3(1024 / 128, 4096 / 128), blk>>>(attn, w_out, out, 1024, 1024);
}

// round 7
// speedup vs baseline: 2.2845x; 1.8802x over previous
#include <cuda_runtime.h>
#include <cuda_bf16.h>
#include <mma.h>
#include <math.h>
#include <stdint.h>

using namespace nvcuda;

// ---------------------------------------------------------------------------
// Scratch (allocation-free rule: device globals)
// ---------------------------------------------------------------------------
__device__ float g_qkv[4096 * 3072];   // [B*S, 3D]  Q|K|V column blocks
__device__ float g_attn[4096 * 1024];  // [B*S, D]   attention output (b,s,(h d))

// ---------------------------------------------------------------------------
// Helpers
// ---------------------------------------------------------------------------
__device__ __forceinline__ uint32_t smem_u32(const void* p) {
    uint32_t a;
    asm("{ .reg .u64 t; cvta.to.shared.u64 t, %1; cvt.u32.u64 %0, t; }" : "=r"(a) : "l"(p));
    return a;
}
__device__ __forceinline__ float ex2(float x) {
    float r; asm("ex2.approx.f32 %0, %1;" : "=f"(r) : "f"(x)); return r;
}
__device__ __forceinline__ uint32_t pack_bf16(float a, float b) {
    __nv_bfloat16 ha = __float2bfloat16_rn(a), hb = __float2bfloat16_rn(b);
    uint16_t ua = *(uint16_t*)&ha, ub = *(uint16_t*)&hb;
    return (uint32_t)ua | ((uint32_t)ub << 16);
}
// split two floats into hi-pair and lo-pair (packed bf16x2)
__device__ __forceinline__ void split2(float x, float y, uint32_t& hi, uint32_t& lo) {
    __nv_bfloat16 hx = __float2bfloat16_rn(x), hy = __float2bfloat16_rn(y);
    float lx = x - __bfloat162float(hx), ly = y - __bfloat162float(hy);
    hi = (uint32_t)(*(uint16_t*)&hx) | ((uint32_t)(*(uint16_t*)&hy) << 16);
    lo = pack_bf16(lx, ly);
}
__device__ __forceinline__ void split4(float4 v, uint2& hi, uint2& lo) {
    split2(v.x, v.y, hi.x, lo.x);
    split2(v.z, v.w, hi.y, lo.y);
}

// m16n8k16 bf16 MMA, fp32 accumulate (fragment layouts per PTX spec)
__device__ __forceinline__ void mma_bf16(float c[4], const uint32_t a[4],
                                         uint32_t b0, uint32_t b1) {
    asm volatile(
        "mma.sync.aligned.m16n8k16.row.col.f32.bf16.bf16.f32 "
        "{%0,%1,%2,%3}, {%4,%5,%6,%7}, {%8,%9}, {%0,%1,%2,%3};"
        : "+f"(c[0]), "+f"(c[1]), "+f"(c[2]), "+f"(c[3])
        : "r"(a[0]), "r"(a[1]), "r"(a[2]), "r"(a[3]), "r"(b0), "r"(b1));
}
__device__ __forceinline__ void ldm_x2_trans(uint32_t& b0, uint32_t& b1, uint32_t addr) {
    asm volatile("ldmatrix.sync.aligned.m8n8.x2.trans.shared.b16 {%0,%1}, [%2];"
                 : "=r"(b0), "=r"(b1) : "r"(addr));
}

// ---------------------------------------------------------------------------
// bf16x3 split GEMM via wmma (unchanged from R6; HMMA base ISA).
//   C[M,N] = A[M,K] @ B[N,K]^T
// ---------------------------------------------------------------------------
#define LDA 24

__global__ __launch_bounds__(256) void gemm_wmma(const float* __restrict__ A,
                                                 const float* __restrict__ B,
                                                 float* __restrict__ C,
                                                 int K, int N) {
    __shared__ alignas(128) __nv_bfloat16 Ah[128 * LDA];
    __shared__ alignas(128) __nv_bfloat16 Al[128 * LDA];
    __shared__ alignas(128) __nv_bfloat16 Bh[128 * LDA];
    __shared__ alignas(128) __nv_bfloat16 Bl[128 * LDA];

    const int tid = threadIdx.x;
    const int wid = tid >> 5;
    const int warp_row = wid >> 2;
    const int warp_col = wid & 3;
    const int row0 = blockIdx.y * 128;
    const int col0 = blockIdx.x * 128;

    wmma::fragment<wmma::accumulator, 16, 16, 16, float> acc[4][2];
#pragma unroll
    for (int i = 0; i < 4; i++)
#pragma unroll
        for (int j = 0; j < 2; j++) wmma::fill_fragment(acc[i][j], 0.0f);

    float4 pa[2], pb[2];
    const int NCH = K >> 4;

    auto gload = [&](int kc) {
#pragma unroll
        for (int i = 0; i < 2; i++) {
            int idx = tid + i * 256;
            int r = idx >> 2;
            int c4 = (idx & 3) << 2;
            pa[i] = *(const float4*)&A[(size_t)(row0 + r) * K + kc * 16 + c4];
            pb[i] = *(const float4*)&B[(size_t)(col0 + r) * K + kc * 16 + c4];
        }
    };
    auto sstore = [&]() {
#pragma unroll
        for (int i = 0; i < 2; i++) {
            int idx = tid + i * 256;
            int r = idx >> 2;
            int c4 = (idx & 3) << 2;
            uint2 hi, lo;
            split4(pa[i], hi, lo);
            *(uint2*)&Ah[r * LDA + c4] = hi;
            *(uint2*)&Al[r * LDA + c4] = lo;
            split4(pb[i], hi, lo);
            *(uint2*)&Bh[r * LDA + c4] = hi;
            *(uint2*)&Bl[r * LDA + c4] = lo;
        }
    };

    gload(0);
    for (int c = 0; c < NCH; c++) {
        __syncthreads();
        sstore();
        __syncthreads();
        if (c + 1 < NCH) gload(c + 1);

        wmma::fragment<wmma::matrix_a, 16, 16, 16, __nv_bfloat16, wmma::row_major> ah[4], al[4];
        wmma::fragment<wmma::matrix_b, 16, 16, 16, __nv_bfloat16, wmma::col_major> bh[2], bl[2];
#pragma unroll
        for (int i = 0; i < 4; i++) {
            int r = warp_row * 64 + i * 16;
            wmma::load_matrix_sync(ah[i], &Ah[r * LDA], LDA);
            wmma::load_matrix_sync(al[i], &Al[r * LDA], LDA);
        }
#pragma unroll
        for (int j = 0; j < 2; j++) {
            int cc = warp_col * 32 + j * 16;
            wmma::load_matrix_sync(bh[j], &Bh[cc * LDA], LDA);
            wmma::load_matrix_sync(bl[j], &Bl[cc * LDA], LDA);
        }
#pragma unroll
        for (int i = 0; i < 4; i++)
#pragma unroll
            for (int j = 0; j < 2; j++) {
                wmma::mma_sync(acc[i][j], ah[i], bh[j], acc[i][j]);
                wmma::mma_sync(acc[i][j], ah[i], bl[j], acc[i][j]);
                wmma::mma_sync(acc[i][j], al[i], bh[j], acc[i][j]);
            }
    }

#pragma unroll
    for (int i = 0; i < 4; i++)
#pragma unroll
        for (int j = 0; j < 2; j++) {
            int r = row0 + warp_row * 64 + i * 16;
            int cc = col0 + warp_col * 32 + j * 16;
            wmma::store_matrix_sync(&C[(size_t)r * N + cc], acc[i][j], N, wmma::mem_row_major);
        }
}

// ---------------------------------------------------------------------------
// Flash attention on tensor cores (bf16x3 split, fp32 softmax state in regs).
// CTA: 128 q-rows for one (b,h). 8 warps x 16 q-rows. 16 key-tiles of 128.
// ---------------------------------------------------------------------------
#define FPIT  72                    // bf16 row pitch (64 data + 8 pad)
#define FTILE (128 * FPIT)          // elems per tile
#define FLASH_SMEM_BYTES (6 * FTILE * 2)   // Qh Ql Kh Kl Vh Vl = 110592 B

__global__ __launch_bounds__(256) void flash_attn(const float* __restrict__ qkv,
                                                  float* __restrict__ attn_out) {
    extern __shared__ __nv_bfloat16 fsm[];
    __nv_bfloat16* Qh = fsm;
    __nv_bfloat16* Ql = Qh + FTILE;
    __nv_bfloat16* Kh = Ql + FTILE;
    __nv_bfloat16* Kl = Kh + FTILE;
    __nv_bfloat16* Vh = Kl + FTILE;
    __nv_bfloat16* Vl = Vh + FTILE;

    const int tid = threadIdx.x;
    const int wid = tid >> 5;
    const int lane = tid & 31;
    const int gr = lane >> 2;        // group row 0..7
    const int qq = lane & 3;         // quad col 0..3

    const int qt = blockIdx.x;               // 0..15 (128 q-rows each)
    const int b  = blockIdx.y >> 4;
    const int h  = blockIdx.y & 15;

    const float* base = qkv + (size_t)b * 2048 * 3072;
    const int qoff = h * 64;
    const int koff = 1024 + h * 64;
    const int voff = 2048 + h * 64;
    const float QSCALE = 0.125f * 1.4426950408889634f;  // 1/sqrt(64) * log2(e)

    // ---- load Q tile (scaled), split to Qh/Ql ----
#pragma unroll
    for (int i = 0; i < 8; i++) {
        int idx = tid + i * 256;      // 0..2047
        int r = idx >> 4;             // 0..127
        int c4 = (idx & 15) << 2;     // 0..60
        float4 v = *(const float4*)&base[(size_t)(qt * 128 + r) * 3072 + qoff + c4];
        v.x *= QSCALE; v.y *= QSCALE; v.z *= QSCALE; v.w *= QSCALE;
        uint2 hi, lo;
        split4(v, hi, lo);
        *(uint2*)&Qh[r * FPIT + c4] = hi;
        *(uint2*)&Ql[r * FPIT + c4] = lo;
    }
    __syncthreads();

    // ---- Q A-fragments (held in regs for all key tiles) ----
    uint32_t qa_h[4][4], qa_l[4][4];
    const int qrow = wid * 16;
#pragma unroll
    for (int kap = 0; kap < 4; kap++) {
        int cb = kap * 16 + 2 * qq;
        qa_h[kap][0] = *(const uint32_t*)&Qh[(qrow + gr) * FPIT + cb];
        qa_h[kap][1] = *(const uint32_t*)&Qh[(qrow + gr + 8) * FPIT + cb];
        qa_h[kap][2] = *(const uint32_t*)&Qh[(qrow + gr) * FPIT + cb + 8];
        qa_h[kap][3] = *(const uint32_t*)&Qh[(qrow + gr + 8) * FPIT + cb + 8];
        qa_l[kap][0] = *(const uint32_t*)&Ql[(qrow + gr) * FPIT + cb];
        qa_l[kap][1] = *(const uint32_t*)&Ql[(qrow + gr + 8) * FPIT + cb];
        qa_l[kap][2] = *(const uint32_t*)&Ql[(qrow + gr) * FPIT + cb + 8];
        qa_l[kap][3] = *(const uint32_t*)&Ql[(qrow + gr + 8) * FPIT + cb + 8];
    }

    float m0 = -1e30f, m1 = -1e30f, l0 = 0.0f, l1 = 0.0f;
    float o[8][4] = {};   // 8 n8-blocks over 64 dims

    const uint32_t vh_base = smem_u32(Vh);
    const uint32_t vl_base = smem_u32(Vl);

    for (int kt = 0; kt < 16; kt++) {
        if (kt > 0) __syncthreads();   // all warps done with previous K/V
        // ---- load K/V tiles, split ----
#pragma unroll
        for (int i = 0; i < 8; i++) {
            int idx = tid + i * 256;
            int r = idx >> 4;
            int c4 = (idx & 15) << 2;
            const float* rowp = &base[(size_t)(kt * 128 + r) * 3072];
            uint2 hi, lo;
            float4 kv = *(const float4*)&rowp[koff + c4];
            split4(kv, hi, lo);
            *(uint2*)&Kh[r * FPIT + c4] = hi;
            *(uint2*)&Kl[r * FPIT + c4] = lo;
            float4 vv = *(const float4*)&rowp[voff + c4];
            split4(vv, hi, lo);
            *(uint2*)&Vh[r * FPIT + c4] = hi;
            *(uint2*)&Vl[r * FPIT + c4] = lo;
        }
        __syncthreads();

        // ---- S = Q @ K^T  (16 n8-blocks of keys) ----
        float S[16][4];
#pragma unroll
        for (int j = 0; j < 16; j++) { S[j][0] = S[j][1] = S[j][2] = S[j][3] = 0.0f; }
#pragma unroll
        for (int j = 0; j < 16; j++) {
            const int krow = (j * 8 + gr) * FPIT;
#pragma unroll
            for (int kap = 0; kap < 4; kap++) {
                int cb = krow + kap * 16 + 2 * qq;
                uint32_t bh0 = *(const uint32_t*)&Kh[cb];
                uint32_t bh1 = *(const uint32_t*)&Kh[cb + 8];
                uint32_t bl0 = *(const uint32_t*)&Kl[cb];
                uint32_t bl1 = *(const uint32_t*)&Kl[cb + 8];
                mma_bf16(S[j], qa_h[kap], bh0, bh1);
                mma_bf16(S[j], qa_h[kap], bl0, bl1);
                mma_bf16(S[j], qa_l[kap], bh0, bh1);
            }
        }

        // ---- online softmax (rows gr and gr+8 of this warp's 16) ----
        float t0 = -1e30f, t1 = -1e30f;
#pragma unroll
        for (int j = 0; j < 16; j++) {
            t0 = fmaxf(t0, fmaxf(S[j][0], S[j][1]));
            t1 = fmaxf(t1, fmaxf(S[j][2], S[j][3]));
        }
        t0 = fmaxf(t0, __shfl_xor_sync(0xffffffffu, t0, 1));
        t0 = fmaxf(t0, __shfl_xor_sync(0xffffffffu, t0, 2));
        t1 = fmaxf(t1, __shfl_xor_sync(0xffffffffu, t1, 1));
        t1 = fmaxf(t1, __shfl_xor_sync(0xffffffffu, t1, 2));
        float mn0 = fmaxf(m0, t0), mn1 = fmaxf(m1, t1);
        float al0 = ex2(m0 - mn0), al1 = ex2(m1 - mn1);
        m0 = mn0; m1 = mn1;

        float rs0 = 0.0f, rs1 = 0.0f;
#pragma unroll
        for (int j = 0; j < 16; j++) {
            S[j][0] = ex2(S[j][0] - m0);
            S[j][1] = ex2(S[j][1] - m0);
            S[j][2] = ex2(S[j][2] - m1);
            S[j][3] = ex2(S[j][3] - m1);
            rs0 += S[j][0] + S[j][1];
            rs1 += S[j][2] + S[j][3];
        }
        rs0 += __shfl_xor_sync(0xffffffffu, rs0, 1);
        rs0 += __shfl_xor_sync(0xffffffffu, rs0, 2);
        rs1 += __shfl_xor_sync(0xffffffffu, rs1, 1);
        rs1 += __shfl_xor_sync(0xffffffffu, rs1, 2);
        l0 = l0 * al0 + rs0;
        l1 = l1 * al1 + rs1;
#pragma unroll
        for (int jn = 0; jn < 8; jn++) {
            o[jn][0] *= al0; o[jn][1] *= al0;
            o[jn][2] *= al1; o[jn][3] *= al1;
        }

        // ---- O += P @ V  (P split in-register; V via ldmatrix.trans) ----
#pragma unroll
        for (int kap = 0; kap < 8; kap++) {
            uint32_t ph[4], pl[4];
            const float* s0 = S[2 * kap];
            const float* s1 = S[2 * kap + 1];
            split2(s0[0], s0[1], ph[0], pl[0]);
            split2(s0[2], s0[3], ph[1], pl[1]);
            split2(s1[0], s1[1], ph[2], pl[2]);
            split2(s1[2], s1[3], ph[3], pl[3]);
            uint32_t va_h = vh_base + (uint32_t)(((kap * 16 + (lane & 15)) * FPIT) * 2);
            uint32_t va_l = vl_base + (uint32_t)(((kap * 16 + (lane & 15)) * FPIT) * 2);
#pragma unroll
            for (int jn = 0; jn < 8; jn++) {
                uint32_t b0, b1, c0, c1;
                ldm_x2_trans(b0, b1, va_h + jn * 16);
                ldm_x2_trans(c0, c1, va_l + jn * 16);
                mma_bf16(o[jn], ph, b0, b1);
                mma_bf16(o[jn], ph, c0, c1);
                mma_bf16(o[jn], pl, b0, b1);
            }
        }
    }

    // ---- epilogue: normalize and store to (b, s, h*64+d) ----
    float inv0 = 1.0f / l0, inv1 = 1.0f / l1;
    const size_t row0 = (size_t)(b * 2048 + qt * 128 + wid * 16 + gr) * 1024 + h * 64;
    const size_t row1 = row0 + 8 * 1024;
#pragma unroll
    for (int jn = 0; jn < 8; jn++) {
        int cc = jn * 8 + 2 * qq;
        *(float2*)&attn_out[row0 + cc] = make_float2(o[jn][0] * inv0, o[jn][1] * inv0);
        *(float2*)&attn_out[row1 + cc] = make_float2(o[jn][2] * inv1, o[jn][3] * inv1);
    }
}

// ---------------------------------------------------------------------------
// Launch
// ---------------------------------------------------------------------------
extern "C" void kernel_launch(void* const* d_in, const int* in_sizes, int n_in,
                              void* d_out, int out_size) {
    const float* x     = (const float*)d_in[0];  // [2,2048,1024]
    const float* w_qkv = (const float*)d_in[1];  // [3072,1024]
    const float* w_out = (const float*)d_in[2];  // [1024,1024]
    float* out = (float*)d_out;                  // [2,2048,1024]

    float* qkv  = nullptr;
    float* attn = nullptr;
    cudaGetSymbolAddress((void**)&qkv, g_qkv);
    cudaGetSymbolAddress((void**)&attn, g_attn);

    cudaFuncSetAttribute(flash_attn, cudaFuncAttributeMaxDynamicSharedMemorySize,
                         FLASH_SMEM_BYTES);

    dim3 blk(256);
    // QKV: [4096,3072] = x[4096,1024] @ w_qkv[3072,1024]^T
    gemm_wmma<<<dim3(3072 / 128, 4096 / 128), blk>>>(x, w_qkv, qkv, 1024, 3072);
    // Attention: 16 q-tiles (128 rows) x (B*H = 32)
    flash_attn<<<dim3(16, 32), blk, FLASH_SMEM_BYTES>>>(qkv, attn);
    // Out: [4096,1024] = attn[4096,1024] @ w_out[1024,1024]^T
    gemm_wmma<<<dim3(1024 / 128, 4096 / 128), blk>>>(attn, w_out, out, 1024, 1024);
}

// round 8
// speedup vs baseline: 2.4299x; 1.0637x over previous
#include <cuda_runtime.h>
#include <cuda_bf16.h>
#include <math.h>
#include <stdint.h>

// ---------------------------------------------------------------------------
// Scratch (allocation-free rule: device globals)
// ---------------------------------------------------------------------------
__device__ float g_qkv[4096 * 3072];            // fp32 qkv (flash input)
__device__ float g_attn[4096 * 1024];           // fp32 attn output
__device__ __nv_bfloat16 g_xh[4096 * 1024],  g_xl[4096 * 1024];
__device__ __nv_bfloat16 g_wqh[3072 * 1024], g_wql[3072 * 1024];
__device__ __nv_bfloat16 g_woh[1024 * 1024], g_wol[1024 * 1024];
__device__ __nv_bfloat16 g_ah[4096 * 1024],  g_al[4096 * 1024];

// ---------------------------------------------------------------------------
// Helpers
// ---------------------------------------------------------------------------
__device__ __forceinline__ uint32_t smem_u32(const void* p) {
    uint32_t a;
    asm("{ .reg .u64 t; cvta.to.shared.u64 t, %1; cvt.u32.u64 %0, t; }" : "=r"(a) : "l"(p));
    return a;
}
__device__ __forceinline__ float ex2(float x) {
    float r; asm("ex2.approx.f32 %0, %1;" : "=f"(r) : "f"(x)); return r;
}
__device__ __forceinline__ uint32_t pack_bf16(float a, float b) {
    __nv_bfloat16 ha = __float2bfloat16_rn(a), hb = __float2bfloat16_rn(b);
    uint16_t ua = *(uint16_t*)&ha, ub = *(uint16_t*)&hb;
    return (uint32_t)ua | ((uint32_t)ub << 16);
}
__device__ __forceinline__ void split2(float x, float y, uint32_t& hi, uint32_t& lo) {
    __nv_bfloat16 hx = __float2bfloat16_rn(x), hy = __float2bfloat16_rn(y);
    float lx = x - __bfloat162float(hx), ly = y - __bfloat162float(hy);
    hi = (uint32_t)(*(uint16_t*)&hx) | ((uint32_t)(*(uint16_t*)&hy) << 16);
    lo = pack_bf16(lx, ly);
}
__device__ __forceinline__ void split4(float4 v, uint2& hi, uint2& lo) {
    split2(v.x, v.y, hi.x, lo.x);
    split2(v.z, v.w, hi.y, lo.y);
}
__device__ __forceinline__ void mma_bf16(float c[4], const uint32_t a[4],
                                         uint32_t b0, uint32_t b1) {
    asm volatile(
        "mma.sync.aligned.m16n8k16.row.col.f32.bf16.bf16.f32 "
        "{%0,%1,%2,%3}, {%4,%5,%6,%7}, {%8,%9}, {%0,%1,%2,%3};"
        : "+f"(c[0]), "+f"(c[1]), "+f"(c[2]), "+f"(c[3])
        : "r"(a[0]), "r"(a[1]), "r"(a[2]), "r"(a[3]), "r"(b0), "r"(b1));
}
__device__ __forceinline__ void ldm_x2_trans(uint32_t& b0, uint32_t& b1, uint32_t addr) {
    asm volatile("ldmatrix.sync.aligned.m8n8.x2.trans.shared.b16 {%0,%1}, [%2];"
                 : "=r"(b0), "=r"(b1) : "r"(addr));
}
__device__ __forceinline__ void ldm_x4(uint32_t r[4], uint32_t addr) {
    asm volatile("ldmatrix.sync.aligned.m8n8.x4.shared.b16 {%0,%1,%2,%3}, [%4];"
                 : "=r"(r[0]), "=r"(r[1]), "=r"(r[2]), "=r"(r[3]) : "r"(addr));
}
__device__ __forceinline__ void cp16(uint32_t saddr, const void* g) {
    asm volatile("cp.async.cg.shared.global [%0], [%1], 16;" :: "r"(saddr), "l"(g));
}

// ---------------------------------------------------------------------------
// split kernel: fp32 -> (hi, lo) bf16 arrays
// ---------------------------------------------------------------------------
__global__ void split_kernel(const float* __restrict__ in,
                             __nv_bfloat16* __restrict__ hi,
                             __nv_bfloat16* __restrict__ lo, int n4) {
    int i = blockIdx.x * blockDim.x + threadIdx.x;
    if (i < n4) {
        float4 v = ((const float4*)in)[i];
        uint2 h, l;
        split4(v, h, l);
        ((uint2*)hi)[i] = h;
        ((uint2*)lo)[i] = l;
    }
}

// ---------------------------------------------------------------------------
// bf16x3 split GEMM, raw mma.sync + ldmatrix + cp.async 3-stage pipeline.
//   C[M,N] = A[M,K] @ B[N,K]^T, A/B given as bf16 hi/lo pairs, C fp32.
// CTA 128x128, BK=32, 8 warps (2x4), warp tile 64x32.
// ---------------------------------------------------------------------------
#define GP     40                    // smem pitch (bf16 elems); 80B rows, conflict-free
#define ARR_B  (128 * GP * 2)        // bytes per array per stage (10240)
#define STG_B  (4 * ARR_B)           // bytes per stage (Ah Al Bh Bl)
#define NSTG   3
#define GEMM_SMEM (NSTG * STG_B)     // 122880 B

__global__ __launch_bounds__(256) void gemm_mma(const __nv_bfloat16* __restrict__ Ahg,
                                                const __nv_bfloat16* __restrict__ Alg,
                                                const __nv_bfloat16* __restrict__ Bhg,
                                                const __nv_bfloat16* __restrict__ Blg,
                                                float* __restrict__ C,
                                                int K, int N) {
    extern __shared__ __align__(16) char gsm[];
    const uint32_t sbase = smem_u32(gsm);

    const int tid = threadIdx.x;
    const int wid = tid >> 5;
    const int lane = tid & 31;
    const int wr = wid >> 2;          // 0..1
    const int wc = wid & 3;           // 0..3
    const int gr = lane >> 2, qq = lane & 3;
    const int row0 = blockIdx.y * 128;
    const int col0 = blockIdx.x * 128;
    const int NCH = K >> 5;

    // cp.async mapping: 8 x 16B per thread per chunk
    // idx = tid + t*256 (t=0..7); arr = idx>>9; i = idx&511; row = i>>2; ch = i&3
    auto load_chunk = [&](int kc, int stg) {
        const uint32_t st = sbase + stg * STG_B;
#pragma unroll
        for (int t = 0; t < 8; t++) {
            int idx = tid + t * 256;
            int arr = idx >> 9;
            int i = idx & 511;
            int row = i >> 2;
            int ch = i & 3;
            uint32_t sa = st + arr * ARR_B + (row * GP + ch * 8) * 2;
            const __nv_bfloat16* gp;
            int kcol = kc * 32 + ch * 8;
            if (arr == 0)      gp = &Ahg[(size_t)(row0 + row) * K + kcol];
            else if (arr == 1) gp = &Alg[(size_t)(row0 + row) * K + kcol];
            else if (arr == 2) gp = &Bhg[(size_t)(col0 + row) * K + kcol];
            else               gp = &Blg[(size_t)(col0 + row) * K + kcol];
            cp16(sa, gp);
        }
    };

    float acc[4][4][4] = {};   // [mi][nj][frag]

    // prologue
#pragma unroll
    for (int s = 0; s < NSTG; s++) {
        load_chunk(s, s);
        asm volatile("cp.async.commit_group;" ::: "memory");
    }

    const uint32_t lrow = lane & 15;
    const uint32_t lcol8 = (lane >> 4) << 3;   // 0 or 8

    for (int c = 0; c < NCH; c++) {
        asm volatile("cp.async.wait_group 2;" ::: "memory");
        __syncthreads();

        const uint32_t st = sbase + (c % NSTG) * STG_B;
        const uint32_t ah = st, al = st + ARR_B, bh = st + 2 * ARR_B, bl = st + 3 * ARR_B;
#pragma unroll
        for (int ks = 0; ks < 2; ks++) {
            const uint32_t koff = (ks * 16 + lcol8) * 2;
            uint32_t fa_h[4][4], fa_l[4][4];
#pragma unroll
            for (int i = 0; i < 4; i++) {
                uint32_t off = ((wr * 64 + i * 16 + lrow) * GP) * 2 + koff;
                ldm_x4(fa_h[i], ah + off);
                ldm_x4(fa_l[i], al + off);
            }
            uint32_t fb_h[4][2], fb_l[4][2];
#pragma unroll
            for (int g = 0; g < 2; g++) {
                uint32_t off = ((wc * 32 + g * 16 + lrow) * GP) * 2 + koff;
                uint32_t r[4];
                ldm_x4(r, bh + off);
                fb_h[2 * g][0] = r[0]; fb_h[2 * g][1] = r[2];
                fb_h[2 * g + 1][0] = r[1]; fb_h[2 * g + 1][1] = r[3];
                ldm_x4(r, bl + off);
                fb_l[2 * g][0] = r[0]; fb_l[2 * g][1] = r[2];
                fb_l[2 * g + 1][0] = r[1]; fb_l[2 * g + 1][1] = r[3];
            }
#pragma unroll
            for (int i = 0; i < 4; i++)
#pragma unroll
                for (int j = 0; j < 4; j++) {
                    mma_bf16(acc[i][j], fa_h[i], fb_h[j][0], fb_h[j][1]);
                    mma_bf16(acc[i][j], fa_h[i], fb_l[j][0], fb_l[j][1]);
                    mma_bf16(acc[i][j], fa_l[i], fb_h[j][0], fb_h[j][1]);
                }
        }
        __syncthreads();
        int nc = c + NSTG;
        if (nc < NCH) load_chunk(nc, c % NSTG);
        asm volatile("cp.async.commit_group;" ::: "memory");
    }

    // epilogue
#pragma unroll
    for (int i = 0; i < 4; i++) {
        int r0g = row0 + wr * 64 + i * 16 + gr;
#pragma unroll
        for (int j = 0; j < 4; j++) {
            int cg = col0 + wc * 32 + j * 8 + 2 * qq;
            *(float2*)&C[(size_t)r0g * N + cg] = make_float2(acc[i][j][0], acc[i][j][1]);
            *(float2*)&C[(size_t)(r0g + 8) * N + cg] = make_float2(acc[i][j][2], acc[i][j][3]);
        }
    }
}

// ---------------------------------------------------------------------------
// Flash attention on tensor cores (unchanged from R7, known-good)
// ---------------------------------------------------------------------------
#define FPIT  72
#define FTILE (128 * FPIT)
#define FLASH_SMEM_BYTES (6 * FTILE * 2)

__global__ __launch_bounds__(256) void flash_attn(const float* __restrict__ qkv,
                                                  float* __restrict__ attn_out) {
    extern __shared__ __nv_bfloat16 fsm[];
    __nv_bfloat16* Qh = fsm;
    __nv_bfloat16* Ql = Qh + FTILE;
    __nv_bfloat16* Kh = Ql + FTILE;
    __nv_bfloat16* Kl = Kh + FTILE;
    __nv_bfloat16* Vh = Kl + FTILE;
    __nv_bfloat16* Vl = Vh + FTILE;

    const int tid = threadIdx.x;
    const int wid = tid >> 5;
    const int lane = tid & 31;
    const int gr = lane >> 2;
    const int qq = lane & 3;

    const int qt = blockIdx.x;
    const int b  = blockIdx.y >> 4;
    const int h  = blockIdx.y & 15;

    const float* base = qkv + (size_t)b * 2048 * 3072;
    const int qoff = h * 64;
    const int koff = 1024 + h * 64;
    const int voff = 2048 + h * 64;
    const float QSCALE = 0.125f * 1.4426950408889634f;

#pragma unroll
    for (int i = 0; i < 8; i++) {
        int idx = tid + i * 256;
        int r = idx >> 4;
        int c4 = (idx & 15) << 2;
        float4 v = *(const float4*)&base[(size_t)(qt * 128 + r) * 3072 + qoff + c4];
        v.x *= QSCALE; v.y *= QSCALE; v.z *= QSCALE; v.w *= QSCALE;
        uint2 hi, lo;
        split4(v, hi, lo);
        *(uint2*)&Qh[r * FPIT + c4] = hi;
        *(uint2*)&Ql[r * FPIT + c4] = lo;
    }
    __syncthreads();

    uint32_t qa_h[4][4], qa_l[4][4];
    const int qrow = wid * 16;
#pragma unroll
    for (int kap = 0; kap < 4; kap++) {
        int cb = kap * 16 + 2 * qq;
        qa_h[kap][0] = *(const uint32_t*)&Qh[(qrow + gr) * FPIT + cb];
        qa_h[kap][1] = *(const uint32_t*)&Qh[(qrow + gr + 8) * FPIT + cb];
        qa_h[kap][2] = *(const uint32_t*)&Qh[(qrow + gr) * FPIT + cb + 8];
        qa_h[kap][3] = *(const uint32_t*)&Qh[(qrow + gr + 8) * FPIT + cb + 8];
        qa_l[kap][0] = *(const uint32_t*)&Ql[(qrow + gr) * FPIT + cb];
        qa_l[kap][1] = *(const uint32_t*)&Ql[(qrow + gr + 8) * FPIT + cb];
        qa_l[kap][2] = *(const uint32_t*)&Ql[(qrow + gr) * FPIT + cb + 8];
        qa_l[kap][3] = *(const uint32_t*)&Ql[(qrow + gr + 8) * FPIT + cb + 8];
    }

    float m0 = -1e30f, m1 = -1e30f, l0 = 0.0f, l1 = 0.0f;
    float o[8][4] = {};

    const uint32_t vh_base = smem_u32(Vh);
    const uint32_t vl_base = smem_u32(Vl);

    for (int kt = 0; kt < 16; kt++) {
        if (kt > 0) __syncthreads();
#pragma unroll
        for (int i = 0; i < 8; i++) {
            int idx = tid + i * 256;
            int r = idx >> 4;
            int c4 = (idx & 15) << 2;
            const float* rowp = &base[(size_t)(kt * 128 + r) * 3072];
            uint2 hi, lo;
            float4 kv = *(const float4*)&rowp[koff + c4];
            split4(kv, hi, lo);
            *(uint2*)&Kh[r * FPIT + c4] = hi;
            *(uint2*)&Kl[r * FPIT + c4] = lo;
            float4 vv = *(const float4*)&rowp[voff + c4];
            split4(vv, hi, lo);
            *(uint2*)&Vh[r * FPIT + c4] = hi;
            *(uint2*)&Vl[r * FPIT + c4] = lo;
        }
        __syncthreads();

        float S[16][4];
#pragma unroll
        for (int j = 0; j < 16; j++) { S[j][0] = S[j][1] = S[j][2] = S[j][3] = 0.0f; }
#pragma unroll
        for (int j = 0; j < 16; j++) {
            const int krow = (j * 8 + gr) * FPIT;
#pragma unroll
            for (int kap = 0; kap < 4; kap++) {
                int cb = krow + kap * 16 + 2 * qq;
                uint32_t bh0 = *(const uint32_t*)&Kh[cb];
                uint32_t bh1 = *(const uint32_t*)&Kh[cb + 8];
                uint32_t bl0 = *(const uint32_t*)&Kl[cb];
                uint32_t bl1 = *(const uint32_t*)&Kl[cb + 8];
                mma_bf16(S[j], qa_h[kap], bh0, bh1);
                mma_bf16(S[j], qa_h[kap], bl0, bl1);
                mma_bf16(S[j], qa_l[kap], bh0, bh1);
            }
        }

        float t0 = -1e30f, t1 = -1e30f;
#pragma unroll
        for (int j = 0; j < 16; j++) {
            t0 = fmaxf(t0, fmaxf(S[j][0], S[j][1]));
            t1 = fmaxf(t1, fmaxf(S[j][2], S[j][3]));
        }
        t0 = fmaxf(t0, __shfl_xor_sync(0xffffffffu, t0, 1));
        t0 = fmaxf(t0, __shfl_xor_sync(0xffffffffu, t0, 2));
        t1 = fmaxf(t1, __shfl_xor_sync(0xffffffffu, t1, 1));
        t1 = fmaxf(t1, __shfl_xor_sync(0xffffffffu, t1, 2));
        float mn0 = fmaxf(m0, t0), mn1 = fmaxf(m1, t1);
        float al0 = ex2(m0 - mn0), al1 = ex2(m1 - mn1);
        m0 = mn0; m1 = mn1;

        float rs0 = 0.0f, rs1 = 0.0f;
#pragma unroll
        for (int j = 0; j < 16; j++) {
            S[j][0] = ex2(S[j][0] - m0);
            S[j][1] = ex2(S[j][1] - m0);
            S[j][2] = ex2(S[j][2] - m1);
            S[j][3] = ex2(S[j][3] - m1);
            rs0 += S[j][0] + S[j][1];
            rs1 += S[j][2] + S[j][3];
        }
        rs0 += __shfl_xor_sync(0xffffffffu, rs0, 1);
        rs0 += __shfl_xor_sync(0xffffffffu, rs0, 2);
        rs1 += __shfl_xor_sync(0xffffffffu, rs1, 1);
        rs1 += __shfl_xor_sync(0xffffffffu, rs1, 2);
        l0 = l0 * al0 + rs0;
        l1 = l1 * al1 + rs1;
#pragma unroll
        for (int jn = 0; jn < 8; jn++) {
            o[jn][0] *= al0; o[jn][1] *= al0;
            o[jn][2] *= al1; o[jn][3] *= al1;
        }

#pragma unroll
        for (int kap = 0; kap < 8; kap++) {
            uint32_t ph[4], pl[4];
            const float* s0 = S[2 * kap];
            const float* s1 = S[2 * kap + 1];
            split2(s0[0], s0[1], ph[0], pl[0]);
            split2(s0[2], s0[3], ph[1], pl[1]);
            split2(s1[0], s1[1], ph[2], pl[2]);
            split2(s1[2], s1[3], ph[3], pl[3]);
            uint32_t va_h = vh_base + (uint32_t)(((kap * 16 + (lane & 15)) * FPIT) * 2);
            uint32_t va_l = vl_base + (uint32_t)(((kap * 16 + (lane & 15)) * FPIT) * 2);
#pragma unroll
            for (int jn = 0; jn < 8; jn++) {
                uint32_t b0, b1, c0, c1;
                ldm_x2_trans(b0, b1, va_h + jn * 16);
                ldm_x2_trans(c0, c1, va_l + jn * 16);
                mma_bf16(o[jn], ph, b0, b1);
                mma_bf16(o[jn], ph, c0, c1);
                mma_bf16(o[jn], pl, b0, b1);
            }
        }
    }

    float inv0 = 1.0f / l0, inv1 = 1.0f / l1;
    const size_t row0 = (size_t)(b * 2048 + qt * 128 + wid * 16 + gr) * 1024 + h * 64;
    const size_t row1 = row0 + 8 * 1024;
#pragma unroll
    for (int jn = 0; jn < 8; jn++) {
        int cc = jn * 8 + 2 * qq;
        *(float2*)&attn_out[row0 + cc] = make_float2(o[jn][0] * inv0, o[jn][1] * inv0);
        *(float2*)&attn_out[row1 + cc] = make_float2(o[jn][2] * inv1, o[jn][3] * inv1);
    }
}

// ---------------------------------------------------------------------------
// Launch: split inputs -> QKV GEMM -> flash -> split attn -> out GEMM
// ---------------------------------------------------------------------------
extern "C" void kernel_launch(void* const* d_in, const int* in_sizes, int n_in,
                              void* d_out, int out_size) {
    const float* x     = (const float*)d_in[0];  // [2,2048,1024]
    const float* w_qkv = (const float*)d_in[1];  // [3072,1024]
    const float* w_out = (const float*)d_in[2];  // [1024,1024]
    float* out = (float*)d_out;                  // [2,2048,1024]

    float *qkv, *attn;
    __nv_bfloat16 *xh, *xl, *wqh, *wql, *woh, *wol, *ah, *al;
    cudaGetSymbolAddress((void**)&qkv, g_qkv);
    cudaGetSymbolAddress((void**)&attn, g_attn);
    cudaGetSymbolAddress((void**)&xh, g_xh);   cudaGetSymbolAddress((void**)&xl, g_xl);
    cudaGetSymbolAddress((void**)&wqh, g_wqh); cudaGetSymbolAddress((void**)&wql, g_wql);
    cudaGetSymbolAddress((void**)&woh, g_woh); cudaGetSymbolAddress((void**)&wol, g_wol);
    cudaGetSymbolAddress((void**)&ah, g_ah);   cudaGetSymbolAddress((void**)&al, g_al);

    cudaFuncSetAttribute(flash_attn, cudaFuncAttributeMaxDynamicSharedMemorySize,
                         FLASH_SMEM_BYTES);
    cudaFuncSetAttribute(gemm_mma, cudaFuncAttributeMaxDynamicSharedMemorySize, GEMM_SMEM);

    dim3 blk(256);
    // split inputs to bf16 hi/lo
    split_kernel<<<(4096 * 1024 / 4 + 255) / 256, blk>>>(x, xh, xl, 4096 * 1024 / 4);
    split_kernel<<<(3072 * 1024 / 4 + 255) / 256, blk>>>(w_qkv, wqh, wql, 3072 * 1024 / 4);
    split_kernel<<<(1024 * 1024 / 4 + 255) / 256, blk>>>(w_out, woh, wol, 1024 * 1024 / 4);
    // QKV: [4096,3072] = x @ w_qkv^T
    gemm_mma<<<dim3(3072 / 128, 4096 / 128), blk, GEMM_SMEM>>>(xh, xl, wqh, wql, qkv, 1024, 3072);
    // Attention
    flash_attn<<<dim3(16, 32), blk, FLASH_SMEM_BYTES>>>(qkv, attn);
    // split attn, then Out: [4096,1024] = attn @ w_out^T
    split_kernel<<<(4096 * 1024 / 4 + 255) / 256, blk>>>(attn, ah, al, 4096 * 1024 / 4);
    gemm_mma<<<dim3(1024 / 128, 4096 / 128), blk, GEMM_SMEM>>>(ah, al, woh, wol, out, 1024, 1024);
}

// round 9
// speedup vs baseline: 2.7318x; 1.1242x over previous
#include <cuda_runtime.h>
#include <cuda_bf16.h>
#include <math.h>
#include <stdint.h>

// ---------------------------------------------------------------------------
// Scratch (allocation-free rule: device globals)
// ---------------------------------------------------------------------------
__device__ __nv_bfloat16 g_xh[4096 * 1024],  g_xl[4096 * 1024];
__device__ __nv_bfloat16 g_wqh[3072 * 1024], g_wql[3072 * 1024];
__device__ __nv_bfloat16 g_woh[1024 * 1024], g_wol[1024 * 1024];
__device__ __nv_bfloat16 g_qh[4096 * 3072],  g_ql[4096 * 3072];   // qkv hi/lo
__device__ __nv_bfloat16 g_ah[4096 * 1024],  g_al[4096 * 1024];   // attn hi/lo

// ---------------------------------------------------------------------------
// Helpers
// ---------------------------------------------------------------------------
__device__ __forceinline__ uint32_t smem_u32(const void* p) {
    uint32_t a;
    asm("{ .reg .u64 t; cvta.to.shared.u64 t, %1; cvt.u32.u64 %0, t; }" : "=r"(a) : "l"(p));
    return a;
}
__device__ __forceinline__ float ex2(float x) {
    float r; asm("ex2.approx.f32 %0, %1;" : "=f"(r) : "f"(x)); return r;
}
__device__ __forceinline__ uint32_t pack_bf16(float a, float b) {
    __nv_bfloat16 ha = __float2bfloat16_rn(a), hb = __float2bfloat16_rn(b);
    uint16_t ua = *(uint16_t*)&ha, ub = *(uint16_t*)&hb;
    return (uint32_t)ua | ((uint32_t)ub << 16);
}
__device__ __forceinline__ void split2(float x, float y, uint32_t& hi, uint32_t& lo) {
    __nv_bfloat16 hx = __float2bfloat16_rn(x), hy = __float2bfloat16_rn(y);
    float lx = x - __bfloat162float(hx), ly = y - __bfloat162float(hy);
    hi = (uint32_t)(*(uint16_t*)&hx) | ((uint32_t)(*(uint16_t*)&hy) << 16);
    lo = pack_bf16(lx, ly);
}
__device__ __forceinline__ void split4(float4 v, uint2& hi, uint2& lo) {
    split2(v.x, v.y, hi.x, lo.x);
    split2(v.z, v.w, hi.y, lo.y);
}
__device__ __forceinline__ void mma_bf16(float c[4], const uint32_t a[4],
                                         uint32_t b0, uint32_t b1) {
    asm volatile(
        "mma.sync.aligned.m16n8k16.row.col.f32.bf16.bf16.f32 "
        "{%0,%1,%2,%3}, {%4,%5,%6,%7}, {%8,%9}, {%0,%1,%2,%3};"
        : "+f"(c[0]), "+f"(c[1]), "+f"(c[2]), "+f"(c[3])
        : "r"(a[0]), "r"(a[1]), "r"(a[2]), "r"(a[3]), "r"(b0), "r"(b1));
}
__device__ __forceinline__ void ldm_x2_trans(uint32_t& b0, uint32_t& b1, uint32_t addr) {
    asm volatile("ldmatrix.sync.aligned.m8n8.x2.trans.shared.b16 {%0,%1}, [%2];"
                 : "=r"(b0), "=r"(b1) : "r"(addr));
}
__device__ __forceinline__ void ldm_x4(uint32_t r[4], uint32_t addr) {
    asm volatile("ldmatrix.sync.aligned.m8n8.x4.shared.b16 {%0,%1,%2,%3}, [%4];"
                 : "=r"(r[0]), "=r"(r[1]), "=r"(r[2]), "=r"(r[3]) : "r"(addr));
}
__device__ __forceinline__ void cp16(uint32_t saddr, const void* g) {
    asm volatile("cp.async.cg.shared.global [%0], [%1], 16;" :: "r"(saddr), "l"(g));
}
#define CP_COMMIT() asm volatile("cp.async.commit_group;" ::: "memory")
#define CP_WAIT1()  asm volatile("cp.async.wait_group 1;" ::: "memory")

// ---------------------------------------------------------------------------
// split kernel: fp32 -> (hi, lo) bf16 arrays
// ---------------------------------------------------------------------------
__global__ void split_kernel(const float* __restrict__ in,
                             __nv_bfloat16* __restrict__ hi,
                             __nv_bfloat16* __restrict__ lo, int n4) {
    int i = blockIdx.x * blockDim.x + threadIdx.x;
    if (i < n4) {
        float4 v = ((const float4*)in)[i];
        uint2 h, l;
        split4(v, h, l);
        ((uint2*)hi)[i] = h;
        ((uint2*)lo)[i] = l;
    }
}

// ---------------------------------------------------------------------------
// bf16x3 split GEMM, raw mma.sync + ldmatrix + cp.async, 2-stage, 2 CTA/SM.
//   C[M,N] = A[M,K] @ B[N,K]^T;  epilogue: fp32 C  OR  bf16 hi/lo split pair.
// ---------------------------------------------------------------------------
#define GP     40
#define ARR_B  (128 * GP * 2)
#define STG_B  (4 * ARR_B)
#define NSTG   2
#define GEMM_SMEM (NSTG * STG_B)     // 81920 B -> 2 CTAs/SM

template <bool SPLITC>
__global__ __launch_bounds__(256, 2) void gemm_mma(const __nv_bfloat16* __restrict__ Ahg,
                                                   const __nv_bfloat16* __restrict__ Alg,
                                                   const __nv_bfloat16* __restrict__ Bhg,
                                                   const __nv_bfloat16* __restrict__ Blg,
                                                   float* __restrict__ C,
                                                   __nv_bfloat16* __restrict__ Ch,
                                                   __nv_bfloat16* __restrict__ Cl,
                                                   int K, int N) {
    extern __shared__ __align__(16) char gsm[];
    const uint32_t sbase = smem_u32(gsm);

    const int tid = threadIdx.x;
    const int wid = tid >> 5;
    const int lane = tid & 31;
    const int wr = wid >> 2;
    const int wc = wid & 3;
    const int gr = lane >> 2, qq = lane & 3;
    const int row0 = blockIdx.y * 128;
    const int col0 = blockIdx.x * 128;
    const int NCH = K >> 5;

    auto load_chunk = [&](int kc, int stg) {
        const uint32_t st = sbase + stg * STG_B;
#pragma unroll
        for (int t = 0; t < 8; t++) {
            int idx = tid + t * 256;
            int arr = idx >> 9;
            int i = idx & 511;
            int row = i >> 2;
            int ch = i & 3;
            uint32_t sa = st + arr * ARR_B + (row * GP + ch * 8) * 2;
            const __nv_bfloat16* gp;
            int kcol = kc * 32 + ch * 8;
            if (arr == 0)      gp = &Ahg[(size_t)(row0 + row) * K + kcol];
            else if (arr == 1) gp = &Alg[(size_t)(row0 + row) * K + kcol];
            else if (arr == 2) gp = &Bhg[(size_t)(col0 + row) * K + kcol];
            else               gp = &Blg[(size_t)(col0 + row) * K + kcol];
            cp16(sa, gp);
        }
    };

    float acc[4][4][4] = {};

    load_chunk(0, 0);
    CP_COMMIT();
    load_chunk(1, 1);
    CP_COMMIT();

    const uint32_t lrow = lane & 15;
    const uint32_t lcol8 = (lane >> 4) << 3;

    for (int c = 0; c < NCH; c++) {
        CP_WAIT1();
        __syncthreads();

        const uint32_t st = sbase + (c & 1) * STG_B;
        const uint32_t ah = st, al = st + ARR_B, bh = st + 2 * ARR_B, bl = st + 3 * ARR_B;
#pragma unroll
        for (int ks = 0; ks < 2; ks++) {
            const uint32_t koff = (ks * 16 + lcol8) * 2;
            uint32_t fa_h[4][4], fa_l[4][4];
#pragma unroll
            for (int i = 0; i < 4; i++) {
                uint32_t off = ((wr * 64 + i * 16 + lrow) * GP) * 2 + koff;
                ldm_x4(fa_h[i], ah + off);
                ldm_x4(fa_l[i], al + off);
            }
            uint32_t fb_h[4][2], fb_l[4][2];
#pragma unroll
            for (int g = 0; g < 2; g++) {
                uint32_t off = ((wc * 32 + g * 16 + lrow) * GP) * 2 + koff;
                uint32_t r[4];
                ldm_x4(r, bh + off);
                fb_h[2 * g][0] = r[0]; fb_h[2 * g][1] = r[2];
                fb_h[2 * g + 1][0] = r[1]; fb_h[2 * g + 1][1] = r[3];
                ldm_x4(r, bl + off);
                fb_l[2 * g][0] = r[0]; fb_l[2 * g][1] = r[2];
                fb_l[2 * g + 1][0] = r[1]; fb_l[2 * g + 1][1] = r[3];
            }
#pragma unroll
            for (int i = 0; i < 4; i++)
#pragma unroll
                for (int j = 0; j < 4; j++) {
                    mma_bf16(acc[i][j], fa_h[i], fb_h[j][0], fb_h[j][1]);
                    mma_bf16(acc[i][j], fa_h[i], fb_l[j][0], fb_l[j][1]);
                    mma_bf16(acc[i][j], fa_l[i], fb_h[j][0], fb_h[j][1]);
                }
        }
        __syncthreads();
        int nc = c + NSTG;
        if (nc < NCH) load_chunk(nc, c & 1);
        CP_COMMIT();
    }

    // epilogue
#pragma unroll
    for (int i = 0; i < 4; i++) {
        int r0g = row0 + wr * 64 + i * 16 + gr;
#pragma unroll
        for (int j = 0; j < 4; j++) {
            int cg = col0 + wc * 32 + j * 8 + 2 * qq;
            if (SPLITC) {
                uint32_t hi, lo;
                split2(acc[i][j][0], acc[i][j][1], hi, lo);
                *(uint32_t*)&Ch[(size_t)r0g * N + cg] = hi;
                *(uint32_t*)&Cl[(size_t)r0g * N + cg] = lo;
                split2(acc[i][j][2], acc[i][j][3], hi, lo);
                *(uint32_t*)&Ch[(size_t)(r0g + 8) * N + cg] = hi;
                *(uint32_t*)&Cl[(size_t)(r0g + 8) * N + cg] = lo;
            } else {
                *(float2*)&C[(size_t)r0g * N + cg] = make_float2(acc[i][j][0], acc[i][j][1]);
                *(float2*)&C[(size_t)(r0g + 8) * N + cg] = make_float2(acc[i][j][2], acc[i][j][3]);
            }
        }
    }
}

// ---------------------------------------------------------------------------
// Flash attention on tensor cores, bf16 hi/lo inputs via cp.async (double-buf).
// CTA: 128 q-rows for one (b,h). 8 warps x 16 q-rows. 16 key-tiles of 128.
// ---------------------------------------------------------------------------
#define FP    72                       // bf16 row pitch (144 B)
#define FT_B  (128 * FP * 2)           // bytes per array (18432)
#define FLASH_SMEM (10 * FT_B)         // Qh Ql + 2 stages x {Kh Kl Vh Vl} = 184320

__global__ __launch_bounds__(256) void flash_attn(const __nv_bfloat16* __restrict__ qh,
                                                  const __nv_bfloat16* __restrict__ ql,
                                                  __nv_bfloat16* __restrict__ oh,
                                                  __nv_bfloat16* __restrict__ ol) {
    extern __shared__ __align__(16) char fsmc[];
    const uint32_t sb = smem_u32(fsmc);
    __nv_bfloat16* Qh = (__nv_bfloat16*)fsmc;
    __nv_bfloat16* Ql = (__nv_bfloat16*)(fsmc + FT_B);

    const int tid = threadIdx.x;
    const int wid = tid >> 5;
    const int lane = tid & 31;
    const int gr = lane >> 2;
    const int qq = lane & 3;

    const int qt = blockIdx.x;
    const int b  = blockIdx.y >> 4;
    const int h  = blockIdx.y & 15;

    const size_t tok0 = (size_t)b * 2048;
    const int qoff = h * 64, koff = 1024 + h * 64, voff = 2048 + h * 64;
    const float QS = 0.125f * 1.4426950408889634f;   // 1/sqrt(64) * log2(e)

    // ---- async load Q (2 arrays x 1024 chunks of 16B) ----
#pragma unroll
    for (int i = 0; i < 8; i++) {
        int idx = tid + i * 256;
        int arr = idx >> 10;
        int rem = idx & 1023;
        int row = rem >> 3, ch = rem & 7;
        const __nv_bfloat16* src = (arr ? ql : qh) +
            (tok0 + qt * 128 + row) * 3072 + qoff + ch * 8;
        cp16(sb + arr * FT_B + row * 144 + ch * 16, src);
    }
    // KV tile loader: stage s in {0,1}; arrays Kh,Kl,Vh,Vl
    auto load_kv = [&](int kt, int s) {
        const uint32_t st = sb + 2 * FT_B + s * 4 * FT_B;
#pragma unroll
        for (int i = 0; i < 16; i++) {
            int idx = tid + i * 256;
            int arr = idx >> 10;
            int rem = idx & 1023;
            int row = rem >> 3, ch = rem & 7;
            int gcol = (arr < 2 ? koff : voff) + ch * 8;
            const __nv_bfloat16* src = ((arr & 1) ? ql : qh) +
                (tok0 + kt * 128 + row) * 3072 + gcol;
            cp16(st + arr * FT_B + row * 144 + ch * 16, src);
        }
    };

    load_kv(0, 0);
    CP_COMMIT();                  // g0: Q + KV0
    load_kv(1, 1);
    CP_COMMIT();                  // g1: KV1
    CP_WAIT1();                   // g0 done
    __syncthreads();

    // ---- Q A-fragments (regs, reused for all key tiles) ----
    uint32_t qa_h[4][4], qa_l[4][4];
    const int qrow = wid * 16;
#pragma unroll
    for (int kap = 0; kap < 4; kap++) {
        int cb = kap * 16 + 2 * qq;
        qa_h[kap][0] = *(const uint32_t*)&Qh[(qrow + gr) * FP + cb];
        qa_h[kap][1] = *(const uint32_t*)&Qh[(qrow + gr + 8) * FP + cb];
        qa_h[kap][2] = *(const uint32_t*)&Qh[(qrow + gr) * FP + cb + 8];
        qa_h[kap][3] = *(const uint32_t*)&Qh[(qrow + gr + 8) * FP + cb + 8];
        qa_l[kap][0] = *(const uint32_t*)&Ql[(qrow + gr) * FP + cb];
        qa_l[kap][1] = *(const uint32_t*)&Ql[(qrow + gr + 8) * FP + cb];
        qa_l[kap][2] = *(const uint32_t*)&Ql[(qrow + gr) * FP + cb + 8];
        qa_l[kap][3] = *(const uint32_t*)&Ql[(qrow + gr + 8) * FP + cb + 8];
    }

    float m0 = -1e30f, m1 = -1e30f, l0 = 0.0f, l1 = 0.0f;
    float o[8][4] = {};

    for (int kt = 0; kt < 16; kt++) {
        const uint32_t st = sb + 2 * FT_B + (kt & 1) * 4 * FT_B;
        const __nv_bfloat16* Kh = (const __nv_bfloat16*)(fsmc + 2 * FT_B + (kt & 1) * 4 * FT_B);
        const __nv_bfloat16* Kl = Kh + 128 * FP;
        const uint32_t vh_u = st + 2 * FT_B;
        const uint32_t vl_u = st + 3 * FT_B;

        // ---- S = Q @ K^T ----
        float S[16][4];
#pragma unroll
        for (int j = 0; j < 16; j++) { S[j][0] = S[j][1] = S[j][2] = S[j][3] = 0.0f; }
#pragma unroll
        for (int j = 0; j < 16; j++) {
            const int krow = (j * 8 + gr) * FP;
#pragma unroll
            for (int kap = 0; kap < 4; kap++) {
                int cb = krow + kap * 16 + 2 * qq;
                uint32_t bh0 = *(const uint32_t*)&Kh[cb];
                uint32_t bh1 = *(const uint32_t*)&Kh[cb + 8];
                uint32_t bl0 = *(const uint32_t*)&Kl[cb];
                uint32_t bl1 = *(const uint32_t*)&Kl[cb + 8];
                mma_bf16(S[j], qa_h[kap], bh0, bh1);
                mma_bf16(S[j], qa_h[kap], bl0, bl1);
                mma_bf16(S[j], qa_l[kap], bh0, bh1);
            }
        }
        // scale (folds 1/sqrt(d) and log2e)
#pragma unroll
        for (int j = 0; j < 16; j++) {
            S[j][0] *= QS; S[j][1] *= QS; S[j][2] *= QS; S[j][3] *= QS;
        }

        // ---- online softmax ----
        float t0 = -1e30f, t1 = -1e30f;
#pragma unroll
        for (int j = 0; j < 16; j++) {
            t0 = fmaxf(t0, fmaxf(S[j][0], S[j][1]));
            t1 = fmaxf(t1, fmaxf(S[j][2], S[j][3]));
        }
        t0 = fmaxf(t0, __shfl_xor_sync(0xffffffffu, t0, 1));
        t0 = fmaxf(t0, __shfl_xor_sync(0xffffffffu, t0, 2));
        t1 = fmaxf(t1, __shfl_xor_sync(0xffffffffu, t1, 1));
        t1 = fmaxf(t1, __shfl_xor_sync(0xffffffffu, t1, 2));
        float mn0 = fmaxf(m0, t0), mn1 = fmaxf(m1, t1);
        float al0 = ex2(m0 - mn0), al1 = ex2(m1 - mn1);
        m0 = mn0; m1 = mn1;

        float rs0 = 0.0f, rs1 = 0.0f;
#pragma unroll
        for (int j = 0; j < 16; j++) {
            S[j][0] = ex2(S[j][0] - m0);
            S[j][1] = ex2(S[j][1] - m0);
            S[j][2] = ex2(S[j][2] - m1);
            S[j][3] = ex2(S[j][3] - m1);
            rs0 += S[j][0] + S[j][1];
            rs1 += S[j][2] + S[j][3];
        }
        rs0 += __shfl_xor_sync(0xffffffffu, rs0, 1);
        rs0 += __shfl_xor_sync(0xffffffffu, rs0, 2);
        rs1 += __shfl_xor_sync(0xffffffffu, rs1, 1);
        rs1 += __shfl_xor_sync(0xffffffffu, rs1, 2);
        l0 = l0 * al0 + rs0;
        l1 = l1 * al1 + rs1;
#pragma unroll
        for (int jn = 0; jn < 8; jn++) {
            o[jn][0] *= al0; o[jn][1] *= al0;
            o[jn][2] *= al1; o[jn][3] *= al1;
        }

        // ---- O += P @ V ----
#pragma unroll
        for (int kap = 0; kap < 8; kap++) {
            uint32_t ph[4], pl[4];
            const float* s0 = S[2 * kap];
            const float* s1 = S[2 * kap + 1];
            split2(s0[0], s0[1], ph[0], pl[0]);
            split2(s0[2], s0[3], ph[1], pl[1]);
            split2(s1[0], s1[1], ph[2], pl[2]);
            split2(s1[2], s1[3], ph[3], pl[3]);
            uint32_t va_h = vh_u + (uint32_t)((kap * 16 + (lane & 15)) * 144);
            uint32_t va_l = vl_u + (uint32_t)((kap * 16 + (lane & 15)) * 144);
#pragma unroll
            for (int jn = 0; jn < 8; jn++) {
                uint32_t b0, b1, c0, c1;
                ldm_x2_trans(b0, b1, va_h + jn * 16);
                ldm_x2_trans(c0, c1, va_l + jn * 16);
                mma_bf16(o[jn], ph, b0, b1);
                mma_bf16(o[jn], ph, c0, c1);
                mma_bf16(o[jn], pl, b0, b1);
            }
        }

        // ---- prefetch KV(kt+2) into this stage ----
        __syncthreads();
        if (kt + 2 < 16) load_kv(kt + 2, kt & 1);
        CP_COMMIT();
        if (kt + 1 < 16) {
            CP_WAIT1();
            __syncthreads();
        }
    }

    // ---- epilogue: normalize, split, store bf16 hi/lo (b, s, h*64+d) ----
    float inv0 = 1.0f / l0, inv1 = 1.0f / l1;
    const size_t row0 = (tok0 + qt * 128 + wid * 16 + gr) * 1024 + h * 64;
    const size_t row1 = row0 + 8 * 1024;
#pragma unroll
    for (int jn = 0; jn < 8; jn++) {
        int cc = jn * 8 + 2 * qq;
        uint32_t hi, lo;
        split2(o[jn][0] * inv0, o[jn][1] * inv0, hi, lo);
        *(uint32_t*)&oh[row0 + cc] = hi;
        *(uint32_t*)&ol[row0 + cc] = lo;
        split2(o[jn][2] * inv1, o[jn][3] * inv1, hi, lo);
        *(uint32_t*)&oh[row1 + cc] = hi;
        *(uint32_t*)&ol[row1 + cc] = lo;
    }
}

// ---------------------------------------------------------------------------
// Launch: split inputs -> QKV GEMM (split out) -> flash (split out) -> out GEMM
// ---------------------------------------------------------------------------
extern "C" void kernel_launch(void* const* d_in, const int* in_sizes, int n_in,
                              void* d_out, int out_size) {
    const float* x     = (const float*)d_in[0];  // [2,2048,1024]
    const float* w_qkv = (const float*)d_in[1];  // [3072,1024]
    const float* w_out = (const float*)d_in[2];  // [1024,1024]
    float* out = (float*)d_out;                  // [2,2048,1024]

    __nv_bfloat16 *xh, *xl, *wqh, *wql, *woh, *wol, *qh, *ql, *ah, *al;
    cudaGetSymbolAddress((void**)&xh, g_xh);   cudaGetSymbolAddress((void**)&xl, g_xl);
    cudaGetSymbolAddress((void**)&wqh, g_wqh); cudaGetSymbolAddress((void**)&wql, g_wql);
    cudaGetSymbolAddress((void**)&woh, g_woh); cudaGetSymbolAddress((void**)&wol, g_wol);
    cudaGetSymbolAddress((void**)&qh, g_qh);   cudaGetSymbolAddress((void**)&ql, g_ql);
    cudaGetSymbolAddress((void**)&ah, g_ah);   cudaGetSymbolAddress((void**)&al, g_al);

    cudaFuncSetAttribute(flash_attn, cudaFuncAttributeMaxDynamicSharedMemorySize, FLASH_SMEM);
    cudaFuncSetAttribute(gemm_mma<true>, cudaFuncAttributeMaxDynamicSharedMemorySize, GEMM_SMEM);
    cudaFuncSetAttribute(gemm_mma<false>, cudaFuncAttributeMaxDynamicSharedMemorySize, GEMM_SMEM);

    dim3 blk(256);
    split_kernel<<<(4096 * 1024 / 4 + 255) / 256, blk>>>(x, xh, xl, 4096 * 1024 / 4);
    split_kernel<<<(3072 * 1024 / 4 + 255) / 256, blk>>>(w_qkv, wqh, wql, 3072 * 1024 / 4);
    split_kernel<<<(1024 * 1024 / 4 + 255) / 256, blk>>>(w_out, woh, wol, 1024 * 1024 / 4);
    // QKV: [4096,3072] = x @ w_qkv^T  -> bf16 hi/lo
    gemm_mma<true><<<dim3(3072 / 128, 4096 / 128), blk, GEMM_SMEM>>>(
        xh, xl, wqh, wql, nullptr, qh, ql, 1024, 3072);
    // Attention -> bf16 hi/lo
    flash_attn<<<dim3(16, 32), blk, FLASH_SMEM>>>(qh, ql, ah, al);
    // Out: [4096,1024] = attn @ w_out^T -> fp32
    gemm_mma<false><<<dim3(1024 / 128, 4096 / 128), blk, GEMM_SMEM>>>(
        ah, al, woh, wol, out, nullptr, nullptr, 1024, 1024);
}

// round 10
// speedup vs baseline: 2.8799x; 1.0542x over previous
#include <cuda_runtime.h>
#include <cuda_bf16.h>
#include <math.h>
#include <stdint.h>

// ---------------------------------------------------------------------------
// Scratch (allocation-free rule: device globals)
// ---------------------------------------------------------------------------
__device__ __nv_bfloat16 g_xh[4096 * 1024],  g_xl[4096 * 1024];
__device__ __nv_bfloat16 g_wqh[3072 * 1024], g_wql[3072 * 1024];
__device__ __nv_bfloat16 g_woh[1024 * 1024], g_wol[1024 * 1024];
__device__ __nv_bfloat16 g_qh[4096 * 3072],  g_ql[4096 * 3072];   // qkv hi/lo
__device__ __nv_bfloat16 g_ah[4096 * 1024],  g_al[4096 * 1024];   // attn hi/lo

// ---------------------------------------------------------------------------
// Helpers
// ---------------------------------------------------------------------------
__device__ __forceinline__ uint32_t smem_u32(const void* p) {
    uint32_t a;
    asm("{ .reg .u64 t; cvta.to.shared.u64 t, %1; cvt.u32.u64 %0, t; }" : "=r"(a) : "l"(p));
    return a;
}
__device__ __forceinline__ float ex2(float x) {
    float r; asm("ex2.approx.f32 %0, %1;" : "=f"(r) : "f"(x)); return r;
}
__device__ __forceinline__ uint32_t pack_bf16(float a, float b) {
    __nv_bfloat16 ha = __float2bfloat16_rn(a), hb = __float2bfloat16_rn(b);
    uint16_t ua = *(uint16_t*)&ha, ub = *(uint16_t*)&hb;
    return (uint32_t)ua | ((uint32_t)ub << 16);
}
__device__ __forceinline__ void split2(float x, float y, uint32_t& hi, uint32_t& lo) {
    __nv_bfloat16 hx = __float2bfloat16_rn(x), hy = __float2bfloat16_rn(y);
    float lx = x - __bfloat162float(hx), ly = y - __bfloat162float(hy);
    hi = (uint32_t)(*(uint16_t*)&hx) | ((uint32_t)(*(uint16_t*)&hy) << 16);
    lo = pack_bf16(lx, ly);
}
__device__ __forceinline__ void split4(float4 v, uint2& hi, uint2& lo) {
    split2(v.x, v.y, hi.x, lo.x);
    split2(v.z, v.w, hi.y, lo.y);
}
__device__ __forceinline__ void mma_bf16(float c[4], const uint32_t a[4],
                                         uint32_t b0, uint32_t b1) {
    asm volatile(
        "mma.sync.aligned.m16n8k16.row.col.f32.bf16.bf16.f32 "
        "{%0,%1,%2,%3}, {%4,%5,%6,%7}, {%8,%9}, {%0,%1,%2,%3};"
        : "+f"(c[0]), "+f"(c[1]), "+f"(c[2]), "+f"(c[3])
        : "r"(a[0]), "r"(a[1]), "r"(a[2]), "r"(a[3]), "r"(b0), "r"(b1));
}
__device__ __forceinline__ void ldm_x2_trans(uint32_t& b0, uint32_t& b1, uint32_t addr) {
    asm volatile("ldmatrix.sync.aligned.m8n8.x2.trans.shared.b16 {%0,%1}, [%2];"
                 : "=r"(b0), "=r"(b1) : "r"(addr));
}
__device__ __forceinline__ void ldm_x4(uint32_t r[4], uint32_t addr) {
    asm volatile("ldmatrix.sync.aligned.m8n8.x4.shared.b16 {%0,%1,%2,%3}, [%4];"
                 : "=r"(r[0]), "=r"(r[1]), "=r"(r[2]), "=r"(r[3]) : "r"(addr));
}
__device__ __forceinline__ void cp16(uint32_t saddr, const void* g) {
    asm volatile("cp.async.cg.shared.global [%0], [%1], 16;" :: "r"(saddr), "l"(g));
}
#define CP_COMMIT() asm volatile("cp.async.commit_group;" ::: "memory")
#define CP_WAIT1()  asm volatile("cp.async.wait_group 1;" ::: "memory")

// ---------------------------------------------------------------------------
// split kernel: fp32 -> (hi, lo) bf16 arrays
// ---------------------------------------------------------------------------
__global__ void split_kernel(const float* __restrict__ in,
                             __nv_bfloat16* __restrict__ hi,
                             __nv_bfloat16* __restrict__ lo, int n4) {
    int i = blockIdx.x * blockDim.x + threadIdx.x;
    if (i < n4) {
        float4 v = ((const float4*)in)[i];
        uint2 h, l;
        split4(v, h, l);
        ((uint2*)hi)[i] = h;
        ((uint2*)lo)[i] = l;
    }
}

// ---------------------------------------------------------------------------
// bf16x3 split GEMM, raw mma.sync + ldmatrix + cp.async, 2-stage, 2 CTA/SM.
//   C[M,N] = A[M,K] @ B[N,K]^T;  epilogue: fp32 C  OR  bf16 hi/lo split pair.
// Inner loop interleaves LDSM with the three MMA term groups.
// ---------------------------------------------------------------------------
#define GP     40
#define ARR_B  (128 * GP * 2)
#define STG_B  (4 * ARR_B)
#define NSTG   2
#define GEMM_SMEM (NSTG * STG_B)     // 81920 B -> 2 CTAs/SM

template <bool SPLITC>
__global__ __launch_bounds__(256, 2) void gemm_mma(const __nv_bfloat16* __restrict__ Ahg,
                                                   const __nv_bfloat16* __restrict__ Alg,
                                                   const __nv_bfloat16* __restrict__ Bhg,
                                                   const __nv_bfloat16* __restrict__ Blg,
                                                   float* __restrict__ C,
                                                   __nv_bfloat16* __restrict__ Ch,
                                                   __nv_bfloat16* __restrict__ Cl,
                                                   int K, int N) {
    extern __shared__ __align__(16) char gsm[];
    const uint32_t sbase = smem_u32(gsm);

    const int tid = threadIdx.x;
    const int wid = tid >> 5;
    const int lane = tid & 31;
    const int wr = wid >> 2;
    const int wc = wid & 3;
    const int gr = lane >> 2, qq = lane & 3;
    const int row0 = blockIdx.y * 128;
    const int col0 = blockIdx.x * 128;
    const int NCH = K >> 5;

    auto load_chunk = [&](int kc, int stg) {
        const uint32_t st = sbase + stg * STG_B;
#pragma unroll
        for (int t = 0; t < 8; t++) {
            int idx = tid + t * 256;
            int arr = idx >> 9;
            int i = idx & 511;
            int row = i >> 2;
            int ch = i & 3;
            uint32_t sa = st + arr * ARR_B + (row * GP + ch * 8) * 2;
            const __nv_bfloat16* gp;
            int kcol = kc * 32 + ch * 8;
            if (arr == 0)      gp = &Ahg[(size_t)(row0 + row) * K + kcol];
            else if (arr == 1) gp = &Alg[(size_t)(row0 + row) * K + kcol];
            else if (arr == 2) gp = &Bhg[(size_t)(col0 + row) * K + kcol];
            else               gp = &Blg[(size_t)(col0 + row) * K + kcol];
            cp16(sa, gp);
        }
    };

    float acc[4][4][4] = {};

    load_chunk(0, 0);
    CP_COMMIT();
    load_chunk(1, 1);
    CP_COMMIT();

    const uint32_t lrow = lane & 15;
    const uint32_t lcol8 = (lane >> 4) << 3;

    for (int c = 0; c < NCH; c++) {
        CP_WAIT1();
        __syncthreads();

        const uint32_t st = sbase + (c & 1) * STG_B;
        const uint32_t ah = st, al = st + ARR_B, bh = st + 2 * ARR_B, bl = st + 3 * ARR_B;
#pragma unroll
        for (int ks = 0; ks < 2; ks++) {
            const uint32_t koff = (ks * 16 + lcol8) * 2;
            // --- term 1: Ah * Bh ---
            uint32_t fa[4][4], fb[4][2];
#pragma unroll
            for (int i = 0; i < 4; i++)
                ldm_x4(fa[i], ah + ((wr * 64 + i * 16 + lrow) * GP) * 2 + koff);
#pragma unroll
            for (int g = 0; g < 2; g++) {
                uint32_t r[4];
                ldm_x4(r, bh + ((wc * 32 + g * 16 + lrow) * GP) * 2 + koff);
                fb[2 * g][0] = r[0]; fb[2 * g][1] = r[2];
                fb[2 * g + 1][0] = r[1]; fb[2 * g + 1][1] = r[3];
            }
#pragma unroll
            for (int i = 0; i < 4; i++)
#pragma unroll
                for (int j = 0; j < 4; j++)
                    mma_bf16(acc[i][j], fa[i], fb[j][0], fb[j][1]);
            // --- term 2: Ah * Bl ---
            uint32_t fbl[4][2];
#pragma unroll
            for (int g = 0; g < 2; g++) {
                uint32_t r[4];
                ldm_x4(r, bl + ((wc * 32 + g * 16 + lrow) * GP) * 2 + koff);
                fbl[2 * g][0] = r[0]; fbl[2 * g][1] = r[2];
                fbl[2 * g + 1][0] = r[1]; fbl[2 * g + 1][1] = r[3];
            }
#pragma unroll
            for (int i = 0; i < 4; i++)
#pragma unroll
                for (int j = 0; j < 4; j++)
                    mma_bf16(acc[i][j], fa[i], fbl[j][0], fbl[j][1]);
            // --- term 3: Al * Bh ---
#pragma unroll
            for (int i = 0; i < 4; i++)
                ldm_x4(fa[i], al + ((wr * 64 + i * 16 + lrow) * GP) * 2 + koff);
#pragma unroll
            for (int i = 0; i < 4; i++)
#pragma unroll
                for (int j = 0; j < 4; j++)
                    mma_bf16(acc[i][j], fa[i], fb[j][0], fb[j][1]);
        }
        __syncthreads();
        int nc = c + NSTG;
        if (nc < NCH) load_chunk(nc, c & 1);
        CP_COMMIT();
    }

    // epilogue
#pragma unroll
    for (int i = 0; i < 4; i++) {
        int r0g = row0 + wr * 64 + i * 16 + gr;
#pragma unroll
        for (int j = 0; j < 4; j++) {
            int cg = col0 + wc * 32 + j * 8 + 2 * qq;
            if (SPLITC) {
                uint32_t hi, lo;
                split2(acc[i][j][0], acc[i][j][1], hi, lo);
                *(uint32_t*)&Ch[(size_t)r0g * N + cg] = hi;
                *(uint32_t*)&Cl[(size_t)r0g * N + cg] = lo;
                split2(acc[i][j][2], acc[i][j][3], hi, lo);
                *(uint32_t*)&Ch[(size_t)(r0g + 8) * N + cg] = hi;
                *(uint32_t*)&Cl[(size_t)(r0g + 8) * N + cg] = lo;
            } else {
                *(float2*)&C[(size_t)r0g * N + cg] = make_float2(acc[i][j][0], acc[i][j][1]);
                *(float2*)&C[(size_t)(r0g + 8) * N + cg] = make_float2(acc[i][j][2], acc[i][j][3]);
            }
        }
    }
}

// ---------------------------------------------------------------------------
// Flash attention on tensor cores, bf16 hi/lo in/out, cp.async double-buffer.
// CTA: 128 q-rows x one (b,h); 8 warps x 16 q-rows; 32 key-tiles of 64.
// smem: Qh Ql (128 rows) + 2 stages x {Kh Kl Vh Vl} (64 rows) = 108 KB -> 2 CTA/SM
// ---------------------------------------------------------------------------
#define FP     72                       // bf16 row pitch (144 B)
#define FQ_B   (128 * FP * 2)           // Q array bytes (18432)
#define KV_B   (64 * FP * 2)            // KV array bytes (9216)
#define KVS_B  (4 * KV_B)               // KV stage bytes (36864)
#define FLASH_SMEM (2 * FQ_B + 2 * KVS_B)   // 110592

__global__ __launch_bounds__(256, 2) void flash_attn(const __nv_bfloat16* __restrict__ qh,
                                                     const __nv_bfloat16* __restrict__ ql,
                                                     __nv_bfloat16* __restrict__ oh,
                                                     __nv_bfloat16* __restrict__ ol) {
    extern __shared__ __align__(16) char fsmc[];
    const uint32_t sb = smem_u32(fsmc);
    __nv_bfloat16* Qh = (__nv_bfloat16*)fsmc;

    const int tid = threadIdx.x;
    const int wid = tid >> 5;
    const int lane = tid & 31;
    const int gr = lane >> 2;
    const int qq = lane & 3;

    const int qt = blockIdx.x;
    const int b  = blockIdx.y >> 4;
    const int h  = blockIdx.y & 15;

    const size_t tok0 = (size_t)b * 2048;
    const int qoff = h * 64, koff = 1024 + h * 64, voff = 2048 + h * 64;
    const float QS = 0.125f * 1.4426950408889634f;   // 1/sqrt(64) * log2(e)

    // ---- async load Q (2 arrays x 128 rows x 8 chunks) ----
#pragma unroll
    for (int i = 0; i < 8; i++) {
        int idx = tid + i * 256;
        int arr = idx >> 10;
        int rem = idx & 1023;
        int row = rem >> 3, ch = rem & 7;
        const __nv_bfloat16* src = (arr ? ql : qh) +
            (tok0 + qt * 128 + row) * 3072 + qoff + ch * 8;
        cp16(sb + arr * FQ_B + row * 144 + ch * 16, src);
    }
    // KV tile loader: 4 arrays x 64 rows x 8 chunks = 2048 -> 8/thread
    auto load_kv = [&](int kt, int s) {
        const uint32_t st = sb + 2 * FQ_B + s * KVS_B;
#pragma unroll
        for (int i = 0; i < 8; i++) {
            int idx = tid + i * 256;
            int arr = idx >> 9;
            int rem = idx & 511;
            int row = rem >> 3, ch = rem & 7;
            int gcol = (arr < 2 ? koff : voff) + ch * 8;
            const __nv_bfloat16* src = ((arr & 1) ? ql : qh) +
                (tok0 + kt * 64 + row) * 3072 + gcol;
            cp16(st + arr * KV_B + row * 144 + ch * 16, src);
        }
    };

    load_kv(0, 0);
    CP_COMMIT();                  // g0: Q + KV0
    load_kv(1, 1);
    CP_COMMIT();                  // g1: KV1
    CP_WAIT1();                   // g0 done
    __syncthreads();

    // ---- Q-hi A-fragments resident in regs; Q-lo reloaded per tile ----
    uint32_t qa_h[4][4];
    const int qrow = wid * 16;
    const uint32_t ql_u = sb + FQ_B;
    const uint32_t qfrag_off = (qrow + (lane & 15)) * 144 + ((lane >> 4) << 3) * 2;
#pragma unroll
    for (int kap = 0; kap < 4; kap++) {
        int cb = kap * 16 + 2 * qq;
        qa_h[kap][0] = *(const uint32_t*)&Qh[(qrow + gr) * FP + cb];
        qa_h[kap][1] = *(const uint32_t*)&Qh[(qrow + gr + 8) * FP + cb];
        qa_h[kap][2] = *(const uint32_t*)&Qh[(qrow + gr) * FP + cb + 8];
        qa_h[kap][3] = *(const uint32_t*)&Qh[(qrow + gr + 8) * FP + cb + 8];
    }

    float m0 = -1e30f, m1 = -1e30f, l0 = 0.0f, l1 = 0.0f;
    float o[8][4] = {};

    for (int kt = 0; kt < 32; kt++) {
        const uint32_t st = sb + 2 * FQ_B + (kt & 1) * KVS_B;
        const __nv_bfloat16* Kh = (const __nv_bfloat16*)(fsmc + 2 * FQ_B + (kt & 1) * KVS_B);
        const __nv_bfloat16* Kl = Kh + 64 * FP;
        const uint32_t vh_u = st + 2 * KV_B;
        const uint32_t vl_u = st + 3 * KV_B;

        // ---- S = Q @ K^T (8 n8-blocks of keys) ----
        float S[8][4];
#pragma unroll
        for (int j = 0; j < 8; j++) { S[j][0] = S[j][1] = S[j][2] = S[j][3] = 0.0f; }
#pragma unroll
        for (int kap = 0; kap < 4; kap++) {
            uint32_t qa_l[4];
            ldm_x4(qa_l, ql_u + qfrag_off + kap * 32);
#pragma unroll
            for (int j = 0; j < 8; j++) {
                int cb = (j * 8 + gr) * FP + kap * 16 + 2 * qq;
                uint32_t bh0 = *(const uint32_t*)&Kh[cb];
                uint32_t bh1 = *(const uint32_t*)&Kh[cb + 8];
                uint32_t bl0 = *(const uint32_t*)&Kl[cb];
                uint32_t bl1 = *(const uint32_t*)&Kl[cb + 8];
                mma_bf16(S[j], qa_h[kap], bh0, bh1);
                mma_bf16(S[j], qa_h[kap], bl0, bl1);
                mma_bf16(S[j], qa_l, bh0, bh1);
            }
        }
#pragma unroll
        for (int j = 0; j < 8; j++) {
            S[j][0] *= QS; S[j][1] *= QS; S[j][2] *= QS; S[j][3] *= QS;
        }

        // ---- online softmax ----
        float t0 = -1e30f, t1 = -1e30f;
#pragma unroll
        for (int j = 0; j < 8; j++) {
            t0 = fmaxf(t0, fmaxf(S[j][0], S[j][1]));
            t1 = fmaxf(t1, fmaxf(S[j][2], S[j][3]));
        }
        t0 = fmaxf(t0, __shfl_xor_sync(0xffffffffu, t0, 1));
        t0 = fmaxf(t0, __shfl_xor_sync(0xffffffffu, t0, 2));
        t1 = fmaxf(t1, __shfl_xor_sync(0xffffffffu, t1, 1));
        t1 = fmaxf(t1, __shfl_xor_sync(0xffffffffu, t1, 2));
        float mn0 = fmaxf(m0, t0), mn1 = fmaxf(m1, t1);
        float al0 = ex2(m0 - mn0), al1 = ex2(m1 - mn1);
        m0 = mn0; m1 = mn1;

        float rs0 = 0.0f, rs1 = 0.0f;
#pragma unroll
        for (int j = 0; j < 8; j++) {
            S[j][0] = ex2(S[j][0] - m0);
            S[j][1] = ex2(S[j][1] - m0);
            S[j][2] = ex2(S[j][2] - m1);
            S[j][3] = ex2(S[j][3] - m1);
            rs0 += S[j][0] + S[j][1];
            rs1 += S[j][2] + S[j][3];
        }
        rs0 += __shfl_xor_sync(0xffffffffu, rs0, 1);
        rs0 += __shfl_xor_sync(0xffffffffu, rs0, 2);
        rs1 += __shfl_xor_sync(0xffffffffu, rs1, 1);
        rs1 += __shfl_xor_sync(0xffffffffu, rs1, 2);
        l0 = l0 * al0 + rs0;
        l1 = l1 * al1 + rs1;
#pragma unroll
        for (int jn = 0; jn < 8; jn++) {
            o[jn][0] *= al0; o[jn][1] *= al0;
            o[jn][2] *= al1; o[jn][3] *= al1;
        }

        // ---- O += P @ V  (4 k16 groups over 64 keys) ----
#pragma unroll
        for (int kap = 0; kap < 4; kap++) {
            uint32_t ph[4], pl[4];
            const float* s0 = S[2 * kap];
            const float* s1 = S[2 * kap + 1];
            split2(s0[0], s0[1], ph[0], pl[0]);
            split2(s0[2], s0[3], ph[1], pl[1]);
            split2(s1[0], s1[1], ph[2], pl[2]);
            split2(s1[2], s1[3], ph[3], pl[3]);
            uint32_t va_h = vh_u + (uint32_t)((kap * 16 + (lane & 15)) * 144);
            uint32_t va_l = vl_u + (uint32_t)((kap * 16 + (lane & 15)) * 144);
#pragma unroll
            for (int jn = 0; jn < 8; jn++) {
                uint32_t b0, b1, c0, c1;
                ldm_x2_trans(b0, b1, va_h + jn * 16);
                ldm_x2_trans(c0, c1, va_l + jn * 16);
                mma_bf16(o[jn], ph, b0, b1);
                mma_bf16(o[jn], ph, c0, c1);
                mma_bf16(o[jn], pl, b0, b1);
            }
        }

        // ---- prefetch KV(kt+2) into the stage just consumed ----
        __syncthreads();
        if (kt + 2 < 32) load_kv(kt + 2, kt & 1);
        CP_COMMIT();
        if (kt + 1 < 32) {
            CP_WAIT1();
            __syncthreads();
        }
    }

    // ---- epilogue: normalize, split, store bf16 hi/lo (b, s, h*64+d) ----
    float inv0 = 1.0f / l0, inv1 = 1.0f / l1;
    const size_t row0 = (tok0 + qt * 128 + wid * 16 + gr) * 1024 + h * 64;
    const size_t row1 = row0 + 8 * 1024;
#pragma unroll
    for (int jn = 0; jn < 8; jn++) {
        int cc = jn * 8 + 2 * qq;
        uint32_t hi, lo;
        split2(o[jn][0] * inv0, o[jn][1] * inv0, hi, lo);
        *(uint32_t*)&oh[row0 + cc] = hi;
        *(uint32_t*)&ol[row0 + cc] = lo;
        split2(o[jn][2] * inv1, o[jn][3] * inv1, hi, lo);
        *(uint32_t*)&oh[row1 + cc] = hi;
        *(uint32_t*)&ol[row1 + cc] = lo;
    }
}

// ---------------------------------------------------------------------------
// Launch: split inputs -> QKV GEMM (split out) -> flash (split out) -> out GEMM
// ---------------------------------------------------------------------------
extern "C" void kernel_launch(void* const* d_in, const int* in_sizes, int n_in,
                              void* d_out, int out_size) {
    const float* x     = (const float*)d_in[0];  // [2,2048,1024]
    const float* w_qkv = (const float*)d_in[1];  // [3072,1024]
    const float* w_out = (const float*)d_in[2];  // [1024,1024]
    float* out = (float*)d_out;                  // [2,2048,1024]

    __nv_bfloat16 *xh, *xl, *wqh, *wql, *woh, *wol, *qh, *ql, *ah, *al;
    cudaGetSymbolAddress((void**)&xh, g_xh);   cudaGetSymbolAddress((void**)&xl, g_xl);
    cudaGetSymbolAddress((void**)&wqh, g_wqh); cudaGetSymbolAddress((void**)&wql, g_wql);
    cudaGetSymbolAddress((void**)&woh, g_woh); cudaGetSymbolAddress((void**)&wol, g_wol);
    cudaGetSymbolAddress((void**)&qh, g_qh);   cudaGetSymbolAddress((void**)&ql, g_ql);
    cudaGetSymbolAddress((void**)&ah, g_ah);   cudaGetSymbolAddress((void**)&al, g_al);

    cudaFuncSetAttribute(flash_attn, cudaFuncAttributeMaxDynamicSharedMemorySize, FLASH_SMEM);
    cudaFuncSetAttribute(gemm_mma<true>, cudaFuncAttributeMaxDynamicSharedMemorySize, GEMM_SMEM);
    cudaFuncSetAttribute(gemm_mma<false>, cudaFuncAttributeMaxDynamicSharedMemorySize, GEMM_SMEM);

    dim3 blk(256);
    split_kernel<<<(4096 * 1024 / 4 + 255) / 256, blk>>>(x, xh, xl, 4096 * 1024 / 4);
    split_kernel<<<(3072 * 1024 / 4 + 255) / 256, blk>>>(w_qkv, wqh, wql, 3072 * 1024 / 4);
    split_kernel<<<(1024 * 1024 / 4 + 255) / 256, blk>>>(w_out, woh, wol, 1024 * 1024 / 4);
    // QKV: [4096,3072] = x @ w_qkv^T  -> bf16 hi/lo
    gemm_mma<true><<<dim3(3072 / 128, 4096 / 128), blk, GEMM_SMEM>>>(
        xh, xl, wqh, wql, nullptr, qh, ql, 1024, 3072);
    // Attention -> bf16 hi/lo
    flash_attn<<<dim3(16, 32), blk, FLASH_SMEM>>>(qh, ql, ah, al);
    // Out: [4096,1024] = attn @ w_out^T -> fp32
    gemm_mma<false><<<dim3(1024 / 128, 4096 / 128), blk, GEMM_SMEM>>>(
        ah, al, woh, wol, out, nullptr, nullptr, 1024, 1024);
}